// round 5
// baseline (speedup 1.0000x reference)
#include <cuda_runtime.h>
#include <cuda_bf16.h>
#include <math.h>
#include <stdint.h>

#define BB 2
#define NN 2048
#define DIM 1024
#define HH 16
#define DH 64
#define NNUL 2
#define JJ (NN + NNUL)
#define SCALE 8.0f
#define LN_EPS 1e-5f
#define MM (BB * NN)          // 4096 rows

typedef __nv_bfloat16 bf16;

// ---------------- scratch ----------------------------------------------------
__device__ float g_qraw[(size_t)MM * DIM];
__device__ float g_kvraw[(size_t)MM * 2 * DIM];
__device__ float g_q[(size_t)BB * HH * NN * DH];
__device__ float g_k[(size_t)BB * HH * JJ * DH];
__device__ float g_v[(size_t)BB * HH * JJ * DH];
// bf16 hi/lo operand buffers
__device__ bf16 g_xh[(size_t)MM * DIM],  g_xl[(size_t)MM * DIM];
__device__ bf16 g_xnh[(size_t)MM * DIM], g_xnl[(size_t)MM * DIM];
__device__ bf16 g_aoh[(size_t)MM * DIM], g_aol[(size_t)MM * DIM];
__device__ bf16 g_wqh[(size_t)DIM * DIM],  g_wql[(size_t)DIM * DIM];    // [N][K]
__device__ bf16 g_wkvh[(size_t)2 * DIM * DIM], g_wkvl[(size_t)2 * DIM * DIM];
__device__ bf16 g_woh[(size_t)DIM * DIM],  g_wol[(size_t)DIM * DIM];

__device__ __forceinline__ void split_bf(float v, bf16& h, bf16& l) {
    h = __float2bfloat16_rn(v);
    l = __float2bfloat16_rn(v - __bfloat162float(h));
}

// ---------------- x -> hi/lo convert ----------------------------------------
__global__ void xconv_kernel(const float* __restrict__ x) {
    int i = blockIdx.x * 256 + threadIdx.x;          // float4 index
    float4 v = *(const float4*)&x[(size_t)i * 4];
    bf16 h[4], l[4];
    split_bf(v.x, h[0], l[0]); split_bf(v.y, h[1], l[1]);
    split_bf(v.z, h[2], l[2]); split_bf(v.w, h[3], l[3]);
    *(uint2*)&g_xh[(size_t)i * 4] = *(uint2*)h;
    *(uint2*)&g_xl[(size_t)i * 4] = *(uint2*)l;
}

// ---------------- W transpose + convert: [K][N] f32 -> [N][K] hi/lo ----------
__global__ void wconv_kernel(const float* __restrict__ W, bf16* __restrict__ Th,
                             bf16* __restrict__ Tl, int K, int N) {
    __shared__ float t[32][33];
    int tx = threadIdx.x, ty = threadIdx.y;
    int n0 = blockIdx.x * 32, k0 = blockIdx.y * 32;
#pragma unroll
    for (int e = 0; e < 4; e++)
        t[ty + 8 * e][tx] = W[(size_t)(k0 + ty + 8 * e) * N + n0 + tx];
    __syncthreads();
#pragma unroll
    for (int e = 0; e < 4; e++) {
        float v = t[tx][ty + 8 * e];                 // W[k0+tx][n0+ty+8e]
        int n = n0 + ty + 8 * e, k = k0 + tx;
        bf16 h, l;
        split_bf(v, h, l);
        Th[(size_t)n * K + k] = h;
        Tl[(size_t)n * K + k] = l;
    }
}

// ---------------- LayerNorm (fused hi/lo output) ----------------------------
__global__ void ln_kernel(const float* __restrict__ x, const float* __restrict__ gma,
                          const float* __restrict__ bta) {
    int row = blockIdx.x;
    const float* xr = x + (size_t)row * DIM;
    float vals[4];
    float s = 0.f, ss = 0.f;
#pragma unroll
    for (int i = 0; i < 4; i++) {
        float v = xr[threadIdx.x + i * 256];
        vals[i] = v;
        s += v;
        ss += v * v;
    }
#pragma unroll
    for (int off = 16; off; off >>= 1) {
        s += __shfl_xor_sync(0xffffffffu, s, off);
        ss += __shfl_xor_sync(0xffffffffu, ss, off);
    }
    __shared__ float rs[8], rss[8];
    int w = threadIdx.x >> 5;
    if ((threadIdx.x & 31) == 0) { rs[w] = s; rss[w] = ss; }
    __syncthreads();
    if (threadIdx.x < 32) {
        float a = (threadIdx.x < 8) ? rs[threadIdx.x] : 0.f;
        float b2 = (threadIdx.x < 8) ? rss[threadIdx.x] : 0.f;
#pragma unroll
        for (int off = 4; off; off >>= 1) {
            a += __shfl_xor_sync(0xffffffffu, a, off);
            b2 += __shfl_xor_sync(0xffffffffu, b2, off);
        }
        if (threadIdx.x == 0) { rs[0] = a; rss[0] = b2; }
    }
    __syncthreads();
    float mu = rs[0] * (1.0f / DIM);
    float var = rss[0] * (1.0f / DIM) - mu * mu;
    float inv = rsqrtf(var + LN_EPS);
#pragma unroll
    for (int i = 0; i < 4; i++) {
        int d = threadIdx.x + i * 256;
        float v = (vals[i] - mu) * inv * gma[d] + bta[d];
        bf16 h, l;
        split_bf(v, h, l);
        g_xnh[(size_t)row * DIM + d] = h;
        g_xnl[(size_t)row * DIM + d] = l;
    }
}

// ---------------- bf16 3-term split GEMM ------------------------------------
// C[M,N] = (Ah+Al)[M,K] @ (Bh+Bl)^T[N,K]^T  with Bt stored [N][K].
// 128x128x32 tiles, cp.async double buffer, 8 warps of 64x32.
#define HSTR 40                        // halves per smem row (conflict-free)
#define ARR_H (128 * HSTR)             // 5120 halves per array
#define STAGE_H (4 * ARR_H)            // Ah,Al,Bh,Bl
#define G3_SMEM (2 * STAGE_H * 2)      // bytes = 81920

__device__ __forceinline__ void cp_async16(void* sdst, const void* gsrc) {
    uint32_t sa = (uint32_t)__cvta_generic_to_shared(sdst);
    asm volatile("cp.async.cg.shared.global [%0], [%1], 16;\n" :: "r"(sa), "l"(gsrc));
}
__device__ __forceinline__ void cp_commit() {
    asm volatile("cp.async.commit_group;\n" ::: "memory");
}
__device__ __forceinline__ void cp_wait0() {
    asm volatile("cp.async.wait_group 0;\n" ::: "memory");
}

#define MMA_BF16(C, A, B0, B1)                                              \
    asm volatile(                                                           \
        "mma.sync.aligned.m16n8k16.row.col.f32.bf16.bf16.f32 "              \
        "{%0,%1,%2,%3}, {%4,%5,%6,%7}, {%8,%9}, {%0,%1,%2,%3};"             \
        : "+f"(C[0]), "+f"(C[1]), "+f"(C[2]), "+f"(C[3])                    \
        : "r"(A[0]), "r"(A[1]), "r"(A[2]), "r"(A[3]), "r"(B0), "r"(B1))

__global__ void __launch_bounds__(256)
bf3gemm(const bf16* __restrict__ Ah, const bf16* __restrict__ Al,
        const bf16* __restrict__ Bh, const bf16* __restrict__ Bl,
        float* __restrict__ C, int M, int N, int K) {
    extern __shared__ bf16 sh[];
    int tid = threadIdx.x, lane = tid & 31, warp = tid >> 5;
    int wm = warp >> 2, wn = warp & 3;
    int row0 = blockIdx.y * 128, col0 = blockIdx.x * 128;
    int fr = lane >> 2, fc = lane & 3;

    float acc[4][4][4];
#pragma unroll
    for (int i = 0; i < 4; i++)
#pragma unroll
        for (int j = 0; j < 4; j++)
#pragma unroll
            for (int r = 0; r < 4; r++) acc[i][j][r] = 0.f;

    int tiles = K / 32;

    // staging macro: 2 chunks (16B) per thread per array
#define STAGE_TILE(st, kg)                                                      \
    do {                                                                        \
        bf16* dst = sh + (st) * STAGE_H;                                        \
        _Pragma("unroll")                                                       \
        for (int t = 0; t < 2; t++) {                                           \
            int c = tid + t * 256;                                              \
            int r = c >> 2, ch = (c & 3) * 8;                                   \
            cp_async16(&dst[0 * ARR_H + r * HSTR + ch],                         \
                       &Ah[(size_t)(row0 + r) * K + (kg) + ch]);                \
            cp_async16(&dst[1 * ARR_H + r * HSTR + ch],                         \
                       &Al[(size_t)(row0 + r) * K + (kg) + ch]);                \
            cp_async16(&dst[2 * ARR_H + r * HSTR + ch],                         \
                       &Bh[(size_t)(col0 + r) * K + (kg) + ch]);                \
            cp_async16(&dst[3 * ARR_H + r * HSTR + ch],                         \
                       &Bl[(size_t)(col0 + r) * K + (kg) + ch]);                \
        }                                                                       \
    } while (0)

    STAGE_TILE(0, 0);
    cp_commit();

    for (int kt = 0; kt < tiles; kt++) {
        cp_wait0();
        __syncthreads();
        if (kt + 1 < tiles) {
            STAGE_TILE((kt + 1) & 1, (kt + 1) * 32);
            cp_commit();
        }
        const bf16* As_h = sh + (kt & 1) * STAGE_H;
        const bf16* As_l = As_h + ARR_H;
        const bf16* Bs_h = As_l + ARR_H;
        const bf16* Bs_l = Bs_h + ARR_H;
#pragma unroll
        for (int kc = 0; kc < 2; kc++) {
            int koff = kc * 16 + 2 * fc;
            uint32_t ah[4][4], al_[4][4], bh[4][2], bl_[4][2];
#pragma unroll
            for (int mt = 0; mt < 4; mt++) {
                int ra = (wm * 64 + mt * 16 + fr) * HSTR;
                ah[mt][0] = *(const uint32_t*)&As_h[ra + koff];
                ah[mt][1] = *(const uint32_t*)&As_h[ra + 8 * HSTR + koff];
                ah[mt][2] = *(const uint32_t*)&As_h[ra + koff + 8];
                ah[mt][3] = *(const uint32_t*)&As_h[ra + 8 * HSTR + koff + 8];
                al_[mt][0] = *(const uint32_t*)&As_l[ra + koff];
                al_[mt][1] = *(const uint32_t*)&As_l[ra + 8 * HSTR + koff];
                al_[mt][2] = *(const uint32_t*)&As_l[ra + koff + 8];
                al_[mt][3] = *(const uint32_t*)&As_l[ra + 8 * HSTR + koff + 8];
            }
#pragma unroll
            for (int nt = 0; nt < 4; nt++) {
                int rb = (wn * 32 + nt * 8 + fr) * HSTR;
                bh[nt][0] = *(const uint32_t*)&Bs_h[rb + koff];
                bh[nt][1] = *(const uint32_t*)&Bs_h[rb + koff + 8];
                bl_[nt][0] = *(const uint32_t*)&Bs_l[rb + koff];
                bl_[nt][1] = *(const uint32_t*)&Bs_l[rb + koff + 8];
            }
#pragma unroll
            for (int mt = 0; mt < 4; mt++)
#pragma unroll
                for (int nt = 0; nt < 4; nt++) {
                    MMA_BF16(acc[mt][nt], ah[mt], bh[nt][0], bh[nt][1]);
                    MMA_BF16(acc[mt][nt], ah[mt], bl_[nt][0], bl_[nt][1]);
                    MMA_BF16(acc[mt][nt], al_[mt], bh[nt][0], bh[nt][1]);
                }
        }
        __syncthreads();
    }

#pragma unroll
    for (int mt = 0; mt < 4; mt++) {
        int row = row0 + wm * 64 + mt * 16 + fr;
#pragma unroll
        for (int nt = 0; nt < 4; nt++) {
            int col = col0 + wn * 32 + nt * 8 + fc * 2;
            *(float2*)&C[(size_t)row * N + col] = make_float2(acc[mt][nt][0], acc[mt][nt][1]);
            *(float2*)&C[(size_t)(row + 8) * N + col] = make_float2(acc[mt][nt][2], acc[mt][nt][3]);
        }
    }
}

// ---------------- preps ------------------------------------------------------
__global__ void qprep_kernel(const float* __restrict__ qs) {
    int gw = blockIdx.x * 4 + (threadIdx.x >> 5);
    int lane = threadIdx.x & 31;
    int h = gw % HH;
    int n = (gw / HH) % NN;
    int b = gw / (HH * NN);
    const float* src = g_qraw + (size_t)(b * NN + n) * DIM + h * DH;
    float v0 = src[lane], v1 = src[lane + 32];
    float ss = v0 * v0 + v1 * v1;
#pragma unroll
    for (int off = 16; off; off >>= 1) ss += __shfl_xor_sync(0xffffffffu, ss, off);
    float inv = 1.0f / fmaxf(sqrtf(ss), 1e-12f);
    float* dst = g_q + (size_t)((b * HH + h) * NN + n) * DH;
    dst[lane] = v0 * inv * qs[lane];
    dst[lane + 32] = v1 * inv * qs[lane + 32];
}

__global__ void kvprep_kernel(const float* __restrict__ ks) {
    int gw = blockIdx.x * 4 + (threadIdx.x >> 5);
    int lane = threadIdx.x & 31;
    int h = gw % HH;
    int n = (gw / HH) % NN;
    int b = gw / (HH * NN);
    const float* row = g_kvraw + (size_t)(b * NN + n) * (2 * DIM);
    float k0 = row[h * DH + lane], k1 = row[h * DH + lane + 32];
    float v0 = row[DIM + h * DH + lane], v1 = row[DIM + h * DH + lane + 32];
    float ss = k0 * k0 + k1 * k1;
#pragma unroll
    for (int off = 16; off; off >>= 1) ss += __shfl_xor_sync(0xffffffffu, ss, off);
    float inv = 1.0f / fmaxf(sqrtf(ss), 1e-12f);
    size_t base = (size_t)((b * HH + h) * JJ + (n + NNUL)) * DH;
    g_k[base + lane] = k0 * inv * ks[lane];
    g_k[base + lane + 32] = k1 * inv * ks[lane + 32];
    g_v[base + lane] = v0;
    g_v[base + lane + 32] = v1;
}

__global__ void nullprep_kernel(const float* __restrict__ null_kv,
                                const float* __restrict__ ks) {
    int w = threadIdx.x >> 5;
    int lane = threadIdx.x & 31;
    int h = w / NNUL;
    int t = w % NNUL;
    const float* base = null_kv + (size_t)h * (2 * NNUL) * DH;
    float k0 = base[(2 * t) * DH + lane];
    float k1 = base[(2 * t) * DH + lane + 32];
    float vv0 = base[(2 * t + 1) * DH + lane];
    float vv1 = base[(2 * t + 1) * DH + lane + 32];
    float ss = k0 * k0 + k1 * k1;
#pragma unroll
    for (int off = 16; off; off >>= 1) ss += __shfl_xor_sync(0xffffffffu, ss, off);
    float inv = 1.0f / fmaxf(sqrtf(ss), 1e-12f);
    for (int b = 0; b < BB; b++) {
        size_t o = (size_t)((b * HH + h) * JJ + t) * DH;
        g_k[o + lane] = k0 * inv * ks[lane];
        g_k[o + lane + 32] = k1 * inv * ks[lane + 32];
        g_v[o + lane] = vv0;
        g_v[o + lane + 32] = vv1;
    }
}

// ---------------- mma attention (epilogue -> hi/lo bf16) ---------------------
#define KSTR 72
#define QSTR 68
#define ATTN_SMEM (4 * 64 * KSTR * 2)

__device__ __forceinline__ uint32_t pack_bf2(float a, float b) {
    __nv_bfloat162 t;
    t.x = __float2bfloat16_rn(a);
    t.y = __float2bfloat16_rn(b);
    return *(uint32_t*)&t;
}

__global__ void __launch_bounds__(128)
attn_mma_kernel() {
    extern __shared__ char sm[];
    bf16* Kh = (bf16*)sm;
    bf16* Kl = Kh + 64 * KSTR;
    bf16* Vh = Kl + 64 * KSTR;
    bf16* Vl = Vh + 64 * KSTR;
    float* Qs = (float*)sm;

    int b = blockIdx.z, h = blockIdx.y;
    int qt = (gridDim.x - 1) - blockIdx.x;
    int tid = threadIdx.x;
    int w = tid >> 5;
    int lane = tid & 31;
    int fr = lane >> 2;
    int fc = lane & 3;

    size_t qbase = (size_t)((b * HH + h) * NN + qt * 64) * DH;
    size_t kvbase = (size_t)(b * HH + h) * JJ * DH;

    for (int i = tid; i < 64 * 16; i += 128) {
        int r = i >> 4, c4 = (i & 15) * 4;
        *(float4*)&Qs[r * QSTR + c4] = *(const float4*)&g_q[qbase + (size_t)r * DH + c4];
    }
    __syncthreads();

    uint32_t qh[4][4], ql[4][4];
#pragma unroll
    for (int kc = 0; kc < 4; kc++) {
        int lr = w * 16 + fr;
        int c = kc * 16 + 2 * fc;
#pragma unroll
        for (int p = 0; p < 4; p++) {
            int rr = lr + (p & 1) * 8;
            int cc = c + (p >> 1) * 8;
            float x0 = Qs[rr * QSTR + cc], x1 = Qs[rr * QSTR + cc + 1];
            float h0 = __bfloat162float(__float2bfloat16_rn(x0));
            float h1 = __bfloat162float(__float2bfloat16_rn(x1));
            qh[kc][p] = pack_bf2(h0, h1);
            ql[kc][p] = pack_bf2(x0 - h0, x1 - h1);
        }
    }

    float O[8][4];
#pragma unroll
    for (int nb = 0; nb < 8; nb++)
#pragma unroll
        for (int r = 0; r < 4; r++) O[nb][r] = 0.f;

    float slope = exp2f(-0.5f * (float)(h + 1));
    int row0g = qt * 64 + w * 16 + fr;
    int row1g = row0g + 8;
    int my0 = row0g + NNUL, my1 = row1g + NNUL;
    float m0 = -1e30f, m1 = -1e30f, l0 = 0.f, l1 = 0.f;

    int nkeys = min(qt * 64 + 64 + NNUL, JJ);

    for (int j0 = 0; j0 < nkeys; j0 += 64) {
        __syncthreads();
        for (int i = tid; i < 64 * 16; i += 128) {
            int r = i >> 4, c4 = (i & 15) * 4;
            int j = j0 + r;
            float4 kk = make_float4(0.f, 0.f, 0.f, 0.f);
            float4 vv = make_float4(0.f, 0.f, 0.f, 0.f);
            if (j < JJ) {
                kk = *(const float4*)&g_k[kvbase + (size_t)j * DH + c4];
                vv = *(const float4*)&g_v[kvbase + (size_t)j * DH + c4];
            }
            float ke[4] = {kk.x, kk.y, kk.z, kk.w};
            float ve[4] = {vv.x, vv.y, vv.z, vv.w};
#pragma unroll
            for (int e = 0; e < 4; e++) {
                bf16 khb = __float2bfloat16_rn(ke[e]);
                Kh[r * KSTR + c4 + e] = khb;
                Kl[r * KSTR + c4 + e] = __float2bfloat16_rn(ke[e] - __bfloat162float(khb));
                bf16 vhb = __float2bfloat16_rn(ve[e]);
                Vh[(c4 + e) * KSTR + r] = vhb;
                Vl[(c4 + e) * KSTR + r] = __float2bfloat16_rn(ve[e] - __bfloat162float(vhb));
            }
        }
        __syncthreads();

        float S[8][4];
#pragma unroll
        for (int nb = 0; nb < 8; nb++)
#pragma unroll
            for (int r = 0; r < 4; r++) S[nb][r] = 0.f;

#pragma unroll
        for (int kc = 0; kc < 4; kc++) {
#pragma unroll
            for (int nb = 0; nb < 8; nb++) {
                int krow = nb * 8 + fr;
                int kcol = kc * 16 + 2 * fc;
                uint32_t b0h = *(uint32_t*)&Kh[krow * KSTR + kcol];
                uint32_t b1h = *(uint32_t*)&Kh[krow * KSTR + kcol + 8];
                uint32_t b0l = *(uint32_t*)&Kl[krow * KSTR + kcol];
                uint32_t b1l = *(uint32_t*)&Kl[krow * KSTR + kcol + 8];
                MMA_BF16(S[nb], qh[kc], b0h, b1h);
                MMA_BF16(S[nb], qh[kc], b0l, b1l);
                MMA_BF16(S[nb], ql[kc], b0h, b1h);
            }
        }

        float mt0 = -1e30f, mt1 = -1e30f;
#pragma unroll
        for (int nb = 0; nb < 8; nb++) {
#pragma unroll
            for (int e = 0; e < 2; e++) {
                int col = j0 + nb * 8 + 2 * fc + e;
                float s0 = S[nb][e] * SCALE + slope * (float)(col - my0);
                if (col > my0) s0 = -1e30f;
                S[nb][e] = s0;
                mt0 = fmaxf(mt0, s0);
                float s1 = S[nb][2 + e] * SCALE + slope * (float)(col - my1);
                if (col > my1) s1 = -1e30f;
                S[nb][2 + e] = s1;
                mt1 = fmaxf(mt1, s1);
            }
        }
#pragma unroll
        for (int off = 1; off <= 2; off <<= 1) {
            mt0 = fmaxf(mt0, __shfl_xor_sync(0xffffffffu, mt0, off));
            mt1 = fmaxf(mt1, __shfl_xor_sync(0xffffffffu, mt1, off));
        }
        float mn0 = fmaxf(m0, mt0), mn1 = fmaxf(m1, mt1);
        float c0 = __expf(m0 - mn0), c1 = __expf(m1 - mn1);
        m0 = mn0; m1 = mn1;

        float ps0 = 0.f, ps1 = 0.f;
#pragma unroll
        for (int nb = 0; nb < 8; nb++) {
#pragma unroll
            for (int e = 0; e < 2; e++) {
                float p0 = __expf(S[nb][e] - m0);
                float p1 = __expf(S[nb][2 + e] - m1);
                S[nb][e] = p0; S[nb][2 + e] = p1;
                ps0 += p0; ps1 += p1;
            }
        }
        l0 = l0 * c0 + ps0;
        l1 = l1 * c1 + ps1;
#pragma unroll
        for (int nb = 0; nb < 8; nb++) {
            O[nb][0] *= c0; O[nb][1] *= c0;
            O[nb][2] *= c1; O[nb][3] *= c1;
        }

        uint32_t ph[4][4], pl[4][4];
#pragma unroll
        for (int kc = 0; kc < 4; kc++) {
#pragma unroll
            for (int p = 0; p < 4; p++) {
                float x0 = S[2 * kc + (p >> 1)][(p & 1) * 2 + 0];
                float x1 = S[2 * kc + (p >> 1)][(p & 1) * 2 + 1];
                float h0 = __bfloat162float(__float2bfloat16_rn(x0));
                float h1 = __bfloat162float(__float2bfloat16_rn(x1));
                ph[kc][p] = pack_bf2(h0, h1);
                pl[kc][p] = pack_bf2(x0 - h0, x1 - h1);
            }
        }

#pragma unroll
        for (int kc = 0; kc < 4; kc++) {
#pragma unroll
            for (int nb = 0; nb < 8; nb++) {
                int drow = nb * 8 + fr;
                int kcol = kc * 16 + 2 * fc;
                uint32_t b0h = *(uint32_t*)&Vh[drow * KSTR + kcol];
                uint32_t b1h = *(uint32_t*)&Vh[drow * KSTR + kcol + 8];
                uint32_t b0l = *(uint32_t*)&Vl[drow * KSTR + kcol];
                uint32_t b1l = *(uint32_t*)&Vl[drow * KSTR + kcol + 8];
                MMA_BF16(O[nb], ph[kc], b0h, b1h);
                MMA_BF16(O[nb], ph[kc], b0l, b1l);
                MMA_BF16(O[nb], pl[kc], b0h, b1h);
            }
        }
    }

#pragma unroll
    for (int off = 1; off <= 2; off <<= 1) {
        l0 += __shfl_xor_sync(0xffffffffu, l0, off);
        l1 += __shfl_xor_sync(0xffffffffu, l1, off);
    }
    float i0 = 1.0f / l0, i1 = 1.0f / l1;
#pragma unroll
    for (int nb = 0; nb < 8; nb++) {
        int col = h * DH + nb * 8 + 2 * fc;
        float o00 = O[nb][0] * i0, o01 = O[nb][1] * i0;
        float o10 = O[nb][2] * i1, o11 = O[nb][3] * i1;
        size_t idx0 = (size_t)(b * NN + row0g) * DIM + col;
        size_t idx1 = (size_t)(b * NN + row1g) * DIM + col;
        float h00 = __bfloat162float(__float2bfloat16_rn(o00));
        float h01 = __bfloat162float(__float2bfloat16_rn(o01));
        float h10 = __bfloat162float(__float2bfloat16_rn(o10));
        float h11 = __bfloat162float(__float2bfloat16_rn(o11));
        *(uint32_t*)&g_aoh[idx0] = pack_bf2(h00, h01);
        *(uint32_t*)&g_aol[idx0] = pack_bf2(o00 - h00, o01 - h01);
        *(uint32_t*)&g_aoh[idx1] = pack_bf2(h10, h11);
        *(uint32_t*)&g_aol[idx1] = pack_bf2(o10 - h10, o11 - h11);
    }
}

// ---------------- launch -----------------------------------------------------
extern "C" void kernel_launch(void* const* d_in, const int* in_sizes, int n_in,
                              void* d_out, int out_size) {
    const float* x = (const float*)d_in[0];
    const float* norm_g = (const float*)d_in[1];
    const float* norm_b = (const float*)d_in[2];
    const float* Wq = (const float*)d_in[3];
    const float* Wkv = (const float*)d_in[4];
    const float* q_scale = (const float*)d_in[5];
    const float* k_scale = (const float*)d_in[6];
    const float* null_kv = (const float*)d_in[7];
    const float* Wout = (const float*)d_in[8];
    float* out = (float*)d_out;

    float *p_qraw, *p_kvraw;
    bf16 *p_xh, *p_xl, *p_xnh, *p_xnl, *p_aoh, *p_aol;
    bf16 *p_wqh, *p_wql, *p_wkvh, *p_wkvl, *p_woh, *p_wol;
    cudaGetSymbolAddress((void**)&p_qraw, g_qraw);
    cudaGetSymbolAddress((void**)&p_kvraw, g_kvraw);
    cudaGetSymbolAddress((void**)&p_xh, g_xh);
    cudaGetSymbolAddress((void**)&p_xl, g_xl);
    cudaGetSymbolAddress((void**)&p_xnh, g_xnh);
    cudaGetSymbolAddress((void**)&p_xnl, g_xnl);
    cudaGetSymbolAddress((void**)&p_aoh, g_aoh);
    cudaGetSymbolAddress((void**)&p_aol, g_aol);
    cudaGetSymbolAddress((void**)&p_wqh, g_wqh);
    cudaGetSymbolAddress((void**)&p_wql, g_wql);
    cudaGetSymbolAddress((void**)&p_wkvh, g_wkvh);
    cudaGetSymbolAddress((void**)&p_wkvl, g_wkvl);
    cudaGetSymbolAddress((void**)&p_woh, g_woh);
    cudaGetSymbolAddress((void**)&p_wol, g_wol);

    static int smem_set = 0;
    if (!smem_set) {
        cudaFuncSetAttribute(bf3gemm, cudaFuncAttributeMaxDynamicSharedMemorySize,
                             G3_SMEM);
        smem_set = 1;
    }

    // conversions
    xconv_kernel<<<(MM * DIM / 4) / 256, 256>>>(x);
    wconv_kernel<<<dim3(DIM / 32, DIM / 32), dim3(32, 8)>>>(Wq, p_wqh, p_wql, DIM, DIM);
    wconv_kernel<<<dim3(2 * DIM / 32, DIM / 32), dim3(32, 8)>>>(Wkv, p_wkvh, p_wkvl, DIM, 2 * DIM);
    wconv_kernel<<<dim3(DIM / 32, DIM / 32), dim3(32, 8)>>>(Wout, p_woh, p_wol, DIM, DIM);
    ln_kernel<<<MM, 256>>>(x, norm_g, norm_b);

    // projections
    bf3gemm<<<dim3(2 * DIM / 128, MM / 128), 256, G3_SMEM>>>(
        p_xh, p_xl, p_wkvh, p_wkvl, p_kvraw, MM, 2 * DIM, DIM);
    bf3gemm<<<dim3(DIM / 128, MM / 128), 256, G3_SMEM>>>(
        p_xnh, p_xnl, p_wqh, p_wql, p_qraw, MM, DIM, DIM);

    // preps
    qprep_kernel<<<(BB * NN * HH) / 4, 128>>>(q_scale);
    kvprep_kernel<<<(BB * NN * HH) / 4, 128>>>(k_scale);
    nullprep_kernel<<<1, HH * NNUL * 32>>>(null_kv, k_scale);

    // attention (emits hi/lo)
    attn_mma_kernel<<<dim3(NN / 64, HH, BB), 128, ATTN_SMEM>>>();

    // output projection
    bf3gemm<<<dim3(DIM / 128, MM / 128), 256, G3_SMEM>>>(
        p_aoh, p_aol, p_woh, p_wol, out, MM, DIM, DIM);
}

// round 6
// speedup vs baseline: 1.2180x; 1.2180x over previous
#include <cuda_runtime.h>
#include <cuda_bf16.h>
#include <math.h>
#include <stdint.h>

#define BB 2
#define NN 2048
#define DIM 1024
#define HH 16
#define DH 64
#define NNUL 2
#define JJ (NN + NNUL)
#define SCALE 8.0f
#define LN_EPS 1e-5f
#define MM (BB * NN)

typedef __nv_bfloat16 bf16;

// ---------------- scratch ----------------------------------------------------
__device__ float g_xt[(size_t)MM * DIM];          // x, tf32-rounded
__device__ float g_xn[(size_t)MM * DIM];          // LayerNorm'd x, tf32-rounded
__device__ float g_wqt[(size_t)DIM * DIM];        // Wq tf32
__device__ float g_wkvt[(size_t)DIM * 2 * DIM];   // Wkv tf32
__device__ float g_wot[(size_t)DIM * DIM];        // Wout tf32
__device__ float g_qraw[(size_t)MM * DIM];
__device__ float g_kvraw[(size_t)MM * 2 * DIM];
__device__ float g_q[(size_t)BB * HH * NN * DH];
__device__ float g_k[(size_t)BB * HH * JJ * DH];
__device__ float g_v[(size_t)BB * HH * JJ * DH];
__device__ float g_ao[(size_t)MM * DIM];          // attention out, tf32-rounded

__device__ __forceinline__ uint32_t to_tf32(float f) {
    uint32_t u;
    asm("cvt.rna.tf32.f32 %0, %1;" : "=r"(u) : "f"(f));
    return u;
}
__device__ __forceinline__ float tf32f(float f) {
    uint32_t u = to_tf32(f);
    return __uint_as_float(u);
}

// ---------------- elementwise tf32 pre-round --------------------------------
__global__ void tfconv_kernel(const float* __restrict__ src, float* __restrict__ dst) {
    size_t i = ((size_t)blockIdx.x * 256 + threadIdx.x) * 4;
    float4 v = *(const float4*)&src[i];
    v.x = tf32f(v.x); v.y = tf32f(v.y); v.z = tf32f(v.z); v.w = tf32f(v.w);
    *(float4*)&dst[i] = v;
}

// ---------------- LayerNorm (emits tf32-rounded xn) -------------------------
__global__ void ln_kernel(const float* __restrict__ x, const float* __restrict__ gma,
                          const float* __restrict__ bta) {
    int row = blockIdx.x;
    const float* xr = x + (size_t)row * DIM;
    float vals[4];
    float s = 0.f, ss = 0.f;
#pragma unroll
    for (int i = 0; i < 4; i++) {
        float v = xr[threadIdx.x + i * 256];
        vals[i] = v;
        s += v;
        ss += v * v;
    }
#pragma unroll
    for (int off = 16; off; off >>= 1) {
        s += __shfl_xor_sync(0xffffffffu, s, off);
        ss += __shfl_xor_sync(0xffffffffu, ss, off);
    }
    __shared__ float rs[8], rss[8];
    int w = threadIdx.x >> 5;
    if ((threadIdx.x & 31) == 0) { rs[w] = s; rss[w] = ss; }
    __syncthreads();
    if (threadIdx.x < 32) {
        float a = (threadIdx.x < 8) ? rs[threadIdx.x] : 0.f;
        float b2 = (threadIdx.x < 8) ? rss[threadIdx.x] : 0.f;
#pragma unroll
        for (int off = 4; off; off >>= 1) {
            a += __shfl_xor_sync(0xffffffffu, a, off);
            b2 += __shfl_xor_sync(0xffffffffu, b2, off);
        }
        if (threadIdx.x == 0) { rs[0] = a; rss[0] = b2; }
    }
    __syncthreads();
    float mu = rs[0] * (1.0f / DIM);
    float var = rss[0] * (1.0f / DIM) - mu * mu;
    float inv = rsqrtf(var + LN_EPS);
#pragma unroll
    for (int i = 0; i < 4; i++) {
        int d = threadIdx.x + i * 256;
        g_xn[(size_t)row * DIM + d] = tf32f((vals[i] - mu) * inv * gma[d] + bta[d]);
    }
}

// ---------------- TF32 GEMM, pre-rounded operands (no cvt in mainloop) ------
#define TBM 128
#define TBN 128
#define TBK 32
#define AS_STRIDE 36
#define BS_STRIDE 136
#define AS_FLOATS (TBM * AS_STRIDE)
#define BS_FLOATS (TBK * BS_STRIDE)
#define STAGE_FLOATS (AS_FLOATS + BS_FLOATS)
#define GEMM_SMEM_BYTES (2 * STAGE_FLOATS * 4)

__device__ __forceinline__ void cp_async16(void* sdst, const void* gsrc) {
    uint32_t sa = (uint32_t)__cvta_generic_to_shared(sdst);
    asm volatile("cp.async.cg.shared.global [%0], [%1], 16;\n" :: "r"(sa), "l"(gsrc));
}
__device__ __forceinline__ void cp_commit() {
    asm volatile("cp.async.commit_group;\n" ::: "memory");
}
__device__ __forceinline__ void cp_wait0() {
    asm volatile("cp.async.wait_group 0;\n" ::: "memory");
}

__global__ void __launch_bounds__(256)
tf32gemm(const float* __restrict__ A, const float* __restrict__ B,
         float* __restrict__ C, int M, int N, int K) {
    extern __shared__ float smem[];
    int tid = threadIdx.x;
    int lane = tid & 31;
    int warp = tid >> 5;
    int wm = warp >> 2;
    int wn = warp & 3;
    int row0 = blockIdx.y * TBM;
    int col0 = blockIdx.x * TBN;

    float acc[4][4][4];
#pragma unroll
    for (int i = 0; i < 4; i++)
#pragma unroll
        for (int j = 0; j < 4; j++)
#pragma unroll
            for (int r = 0; r < 4; r++) acc[i][j][r] = 0.f;

    int a_m = tid >> 3;
    int a_k4 = (tid & 7) * 4;
    int b_k = tid >> 5;
    int b_n4 = (tid & 31) * 4;
    int tiles = K / TBK;

    {
        float* As = smem;
        float* Bs = smem + AS_FLOATS;
#pragma unroll
        for (int t = 0; t < 4; t++) {
            int m = a_m + t * 32;
            cp_async16(&As[m * AS_STRIDE + a_k4], &A[(size_t)(row0 + m) * K + a_k4]);
        }
#pragma unroll
        for (int t = 0; t < 4; t++) {
            int k = b_k + t * 8;
            cp_async16(&Bs[k * BS_STRIDE + b_n4], &B[(size_t)k * N + col0 + b_n4]);
        }
        cp_commit();
    }

    for (int kt = 0; kt < tiles; kt++) {
        cp_wait0();
        __syncthreads();
        if (kt + 1 < tiles) {
            float* As = smem + ((kt + 1) & 1) * STAGE_FLOATS;
            float* Bs = As + AS_FLOATS;
            int kg = (kt + 1) * TBK;
#pragma unroll
            for (int t = 0; t < 4; t++) {
                int m = a_m + t * 32;
                cp_async16(&As[m * AS_STRIDE + a_k4], &A[(size_t)(row0 + m) * K + kg + a_k4]);
            }
#pragma unroll
            for (int t = 0; t < 4; t++) {
                int k = b_k + t * 8;
                cp_async16(&Bs[k * BS_STRIDE + b_n4], &B[(size_t)(kg + k) * N + col0 + b_n4]);
            }
            cp_commit();
        }
        const uint32_t* As = (const uint32_t*)(smem + (kt & 1) * STAGE_FLOATS);
        const uint32_t* Bs = As + AS_FLOATS;
        int fr = lane >> 2;
        int fc = lane & 3;
#pragma unroll
        for (int ks = 0; ks < 4; ks++) {
            int kb = ks * 8;
            uint32_t af[4][4], bf[4][2];
#pragma unroll
            for (int mt = 0; mt < 4; mt++) {
                int mb = wm * 64 + mt * 16;
                af[mt][0] = As[(mb + fr) * AS_STRIDE + kb + fc];
                af[mt][1] = As[(mb + 8 + fr) * AS_STRIDE + kb + fc];
                af[mt][2] = As[(mb + fr) * AS_STRIDE + kb + 4 + fc];
                af[mt][3] = As[(mb + 8 + fr) * AS_STRIDE + kb + 4 + fc];
            }
#pragma unroll
            for (int nt = 0; nt < 4; nt++) {
                int nb = wn * 32 + nt * 8;
                bf[nt][0] = Bs[(kb + fc) * BS_STRIDE + nb + fr];
                bf[nt][1] = Bs[(kb + 4 + fc) * BS_STRIDE + nb + fr];
            }
#pragma unroll
            for (int mt = 0; mt < 4; mt++)
#pragma unroll
                for (int nt = 0; nt < 4; nt++) {
                    asm volatile(
                        "mma.sync.aligned.m16n8k8.row.col.f32.tf32.tf32.f32 "
                        "{%0,%1,%2,%3}, {%4,%5,%6,%7}, {%8,%9}, {%0,%1,%2,%3};"
                        : "+f"(acc[mt][nt][0]), "+f"(acc[mt][nt][1]),
                          "+f"(acc[mt][nt][2]), "+f"(acc[mt][nt][3])
                        : "r"(af[mt][0]), "r"(af[mt][1]), "r"(af[mt][2]), "r"(af[mt][3]),
                          "r"(bf[nt][0]), "r"(bf[nt][1]));
                }
        }
        __syncthreads();
    }

    int fr = lane >> 2;
    int fc = lane & 3;
#pragma unroll
    for (int mt = 0; mt < 4; mt++) {
        int row = row0 + wm * 64 + mt * 16 + fr;
#pragma unroll
        for (int nt = 0; nt < 4; nt++) {
            int col = col0 + wn * 32 + nt * 8 + fc * 2;
            *(float2*)&C[(size_t)row * N + col] = make_float2(acc[mt][nt][0], acc[mt][nt][1]);
            *(float2*)&C[(size_t)(row + 8) * N + col] = make_float2(acc[mt][nt][2], acc[mt][nt][3]);
        }
    }
}

// ---------------- preps ------------------------------------------------------
__global__ void qprep_kernel(const float* __restrict__ qs) {
    int gw = blockIdx.x * 4 + (threadIdx.x >> 5);
    int lane = threadIdx.x & 31;
    int h = gw % HH;
    int n = (gw / HH) % NN;
    int b = gw / (HH * NN);
    const float* src = g_qraw + (size_t)(b * NN + n) * DIM + h * DH;
    float v0 = src[lane], v1 = src[lane + 32];
    float ss = v0 * v0 + v1 * v1;
#pragma unroll
    for (int off = 16; off; off >>= 1) ss += __shfl_xor_sync(0xffffffffu, ss, off);
    float inv = 1.0f / fmaxf(sqrtf(ss), 1e-12f);
    float* dst = g_q + (size_t)((b * HH + h) * NN + n) * DH;
    dst[lane] = v0 * inv * qs[lane];
    dst[lane + 32] = v1 * inv * qs[lane + 32];
}

__global__ void kvprep_kernel(const float* __restrict__ ks) {
    int gw = blockIdx.x * 4 + (threadIdx.x >> 5);
    int lane = threadIdx.x & 31;
    int h = gw % HH;
    int n = (gw / HH) % NN;
    int b = gw / (HH * NN);
    const float* row = g_kvraw + (size_t)(b * NN + n) * (2 * DIM);
    float k0 = row[h * DH + lane], k1 = row[h * DH + lane + 32];
    float v0 = row[DIM + h * DH + lane], v1 = row[DIM + h * DH + lane + 32];
    float ss = k0 * k0 + k1 * k1;
#pragma unroll
    for (int off = 16; off; off >>= 1) ss += __shfl_xor_sync(0xffffffffu, ss, off);
    float inv = 1.0f / fmaxf(sqrtf(ss), 1e-12f);
    size_t base = (size_t)((b * HH + h) * JJ + (n + NNUL)) * DH;
    g_k[base + lane] = k0 * inv * ks[lane];
    g_k[base + lane + 32] = k1 * inv * ks[lane + 32];
    g_v[base + lane] = v0;
    g_v[base + lane + 32] = v1;
}

__global__ void nullprep_kernel(const float* __restrict__ null_kv,
                                const float* __restrict__ ks) {
    int w = threadIdx.x >> 5;
    int lane = threadIdx.x & 31;
    int h = w / NNUL;
    int t = w % NNUL;
    const float* base = null_kv + (size_t)h * (2 * NNUL) * DH;
    float k0 = base[(2 * t) * DH + lane];
    float k1 = base[(2 * t) * DH + lane + 32];
    float vv0 = base[(2 * t + 1) * DH + lane];
    float vv1 = base[(2 * t + 1) * DH + lane + 32];
    float ss = k0 * k0 + k1 * k1;
#pragma unroll
    for (int off = 16; off; off >>= 1) ss += __shfl_xor_sync(0xffffffffu, ss, off);
    float inv = 1.0f / fmaxf(sqrtf(ss), 1e-12f);
    for (int b = 0; b < BB; b++) {
        size_t o = (size_t)((b * HH + h) * JJ + t) * DH;
        g_k[o + lane] = k0 * inv * ks[lane];
        g_k[o + lane + 32] = k1 * inv * ks[lane + 32];
        g_v[o + lane] = vv0;
        g_v[o + lane + 32] = vv1;
    }
}

// ---------------- mma attention (epilogue emits tf32-rounded out) -----------
#define KSTR 72
#define QSTR 68
#define ATTN_SMEM (4 * 64 * KSTR * 2)

#define MMA_BF16(C, A, B0, B1)                                              \
    asm volatile(                                                           \
        "mma.sync.aligned.m16n8k16.row.col.f32.bf16.bf16.f32 "              \
        "{%0,%1,%2,%3}, {%4,%5,%6,%7}, {%8,%9}, {%0,%1,%2,%3};"             \
        : "+f"(C[0]), "+f"(C[1]), "+f"(C[2]), "+f"(C[3])                    \
        : "r"(A[0]), "r"(A[1]), "r"(A[2]), "r"(A[3]), "r"(B0), "r"(B1))

__device__ __forceinline__ uint32_t pack_bf2(float a, float b) {
    __nv_bfloat162 t;
    t.x = __float2bfloat16_rn(a);
    t.y = __float2bfloat16_rn(b);
    return *(uint32_t*)&t;
}

__global__ void __launch_bounds__(128)
attn_mma_kernel() {
    extern __shared__ char sm[];
    bf16* Kh = (bf16*)sm;
    bf16* Kl = Kh + 64 * KSTR;
    bf16* Vh = Kl + 64 * KSTR;
    bf16* Vl = Vh + 64 * KSTR;
    float* Qs = (float*)sm;

    int b = blockIdx.z, h = blockIdx.y;
    int qt = (gridDim.x - 1) - blockIdx.x;
    int tid = threadIdx.x;
    int w = tid >> 5;
    int lane = tid & 31;
    int fr = lane >> 2;
    int fc = lane & 3;

    size_t qbase = (size_t)((b * HH + h) * NN + qt * 64) * DH;
    size_t kvbase = (size_t)(b * HH + h) * JJ * DH;

    for (int i = tid; i < 64 * 16; i += 128) {
        int r = i >> 4, c4 = (i & 15) * 4;
        *(float4*)&Qs[r * QSTR + c4] = *(const float4*)&g_q[qbase + (size_t)r * DH + c4];
    }
    __syncthreads();

    uint32_t qh[4][4], ql[4][4];
#pragma unroll
    for (int kc = 0; kc < 4; kc++) {
        int lr = w * 16 + fr;
        int c = kc * 16 + 2 * fc;
#pragma unroll
        for (int p = 0; p < 4; p++) {
            int rr = lr + (p & 1) * 8;
            int cc = c + (p >> 1) * 8;
            float x0 = Qs[rr * QSTR + cc], x1 = Qs[rr * QSTR + cc + 1];
            float h0 = __bfloat162float(__float2bfloat16_rn(x0));
            float h1 = __bfloat162float(__float2bfloat16_rn(x1));
            qh[kc][p] = pack_bf2(h0, h1);
            ql[kc][p] = pack_bf2(x0 - h0, x1 - h1);
        }
    }

    float O[8][4];
#pragma unroll
    for (int nb = 0; nb < 8; nb++)
#pragma unroll
        for (int r = 0; r < 4; r++) O[nb][r] = 0.f;

    float slope = exp2f(-0.5f * (float)(h + 1));
    int row0g = qt * 64 + w * 16 + fr;
    int row1g = row0g + 8;
    int my0 = row0g + NNUL, my1 = row1g + NNUL;
    float m0 = -1e30f, m1 = -1e30f, l0 = 0.f, l1 = 0.f;

    int nkeys = min(qt * 64 + 64 + NNUL, JJ);

    for (int j0 = 0; j0 < nkeys; j0 += 64) {
        __syncthreads();
        for (int i = tid; i < 64 * 16; i += 128) {
            int r = i >> 4, c4 = (i & 15) * 4;
            int j = j0 + r;
            float4 kk = make_float4(0.f, 0.f, 0.f, 0.f);
            float4 vv = make_float4(0.f, 0.f, 0.f, 0.f);
            if (j < JJ) {
                kk = *(const float4*)&g_k[kvbase + (size_t)j * DH + c4];
                vv = *(const float4*)&g_v[kvbase + (size_t)j * DH + c4];
            }
            float ke[4] = {kk.x, kk.y, kk.z, kk.w};
            float ve[4] = {vv.x, vv.y, vv.z, vv.w};
#pragma unroll
            for (int e = 0; e < 4; e++) {
                bf16 khb = __float2bfloat16_rn(ke[e]);
                Kh[r * KSTR + c4 + e] = khb;
                Kl[r * KSTR + c4 + e] = __float2bfloat16_rn(ke[e] - __bfloat162float(khb));
                bf16 vhb = __float2bfloat16_rn(ve[e]);
                Vh[(c4 + e) * KSTR + r] = vhb;
                Vl[(c4 + e) * KSTR + r] = __float2bfloat16_rn(ve[e] - __bfloat162float(vhb));
            }
        }
        __syncthreads();

        float S[8][4];
#pragma unroll
        for (int nb = 0; nb < 8; nb++)
#pragma unroll
            for (int r = 0; r < 4; r++) S[nb][r] = 0.f;

#pragma unroll
        for (int kc = 0; kc < 4; kc++) {
#pragma unroll
            for (int nb = 0; nb < 8; nb++) {
                int krow = nb * 8 + fr;
                int kcol = kc * 16 + 2 * fc;
                uint32_t b0h = *(uint32_t*)&Kh[krow * KSTR + kcol];
                uint32_t b1h = *(uint32_t*)&Kh[krow * KSTR + kcol + 8];
                uint32_t b0l = *(uint32_t*)&Kl[krow * KSTR + kcol];
                uint32_t b1l = *(uint32_t*)&Kl[krow * KSTR + kcol + 8];
                MMA_BF16(S[nb], qh[kc], b0h, b1h);
                MMA_BF16(S[nb], qh[kc], b0l, b1l);
                MMA_BF16(S[nb], ql[kc], b0h, b1h);
            }
        }

        float mt0 = -1e30f, mt1 = -1e30f;
#pragma unroll
        for (int nb = 0; nb < 8; nb++) {
#pragma unroll
            for (int e = 0; e < 2; e++) {
                int col = j0 + nb * 8 + 2 * fc + e;
                float s0 = S[nb][e] * SCALE + slope * (float)(col - my0);
                if (col > my0) s0 = -1e30f;
                S[nb][e] = s0;
                mt0 = fmaxf(mt0, s0);
                float s1 = S[nb][2 + e] * SCALE + slope * (float)(col - my1);
                if (col > my1) s1 = -1e30f;
                S[nb][2 + e] = s1;
                mt1 = fmaxf(mt1, s1);
            }
        }
#pragma unroll
        for (int off = 1; off <= 2; off <<= 1) {
            mt0 = fmaxf(mt0, __shfl_xor_sync(0xffffffffu, mt0, off));
            mt1 = fmaxf(mt1, __shfl_xor_sync(0xffffffffu, mt1, off));
        }
        float mn0 = fmaxf(m0, mt0), mn1 = fmaxf(m1, mt1);
        float c0 = __expf(m0 - mn0), c1 = __expf(m1 - mn1);
        m0 = mn0; m1 = mn1;

        float ps0 = 0.f, ps1 = 0.f;
#pragma unroll
        for (int nb = 0; nb < 8; nb++) {
#pragma unroll
            for (int e = 0; e < 2; e++) {
                float p0 = __expf(S[nb][e] - m0);
                float p1 = __expf(S[nb][2 + e] - m1);
                S[nb][e] = p0; S[nb][2 + e] = p1;
                ps0 += p0; ps1 += p1;
            }
        }
        l0 = l0 * c0 + ps0;
        l1 = l1 * c1 + ps1;
#pragma unroll
        for (int nb = 0; nb < 8; nb++) {
            O[nb][0] *= c0; O[nb][1] *= c0;
            O[nb][2] *= c1; O[nb][3] *= c1;
        }

        uint32_t ph[4][4], pl[4][4];
#pragma unroll
        for (int kc = 0; kc < 4; kc++) {
#pragma unroll
            for (int p = 0; p < 4; p++) {
                float x0 = S[2 * kc + (p >> 1)][(p & 1) * 2 + 0];
                float x1 = S[2 * kc + (p >> 1)][(p & 1) * 2 + 1];
                float h0 = __bfloat162float(__float2bfloat16_rn(x0));
                float h1 = __bfloat162float(__float2bfloat16_rn(x1));
                ph[kc][p] = pack_bf2(h0, h1);
                pl[kc][p] = pack_bf2(x0 - h0, x1 - h1);
            }
        }

#pragma unroll
        for (int kc = 0; kc < 4; kc++) {
#pragma unroll
            for (int nb = 0; nb < 8; nb++) {
                int drow = nb * 8 + fr;
                int kcol = kc * 16 + 2 * fc;
                uint32_t b0h = *(uint32_t*)&Vh[drow * KSTR + kcol];
                uint32_t b1h = *(uint32_t*)&Vh[drow * KSTR + kcol + 8];
                uint32_t b0l = *(uint32_t*)&Vl[drow * KSTR + kcol];
                uint32_t b1l = *(uint32_t*)&Vl[drow * KSTR + kcol + 8];
                MMA_BF16(O[nb], ph[kc], b0h, b1h);
                MMA_BF16(O[nb], ph[kc], b0l, b1l);
                MMA_BF16(O[nb], pl[kc], b0h, b1h);
            }
        }
    }

#pragma unroll
    for (int off = 1; off <= 2; off <<= 1) {
        l0 += __shfl_xor_sync(0xffffffffu, l0, off);
        l1 += __shfl_xor_sync(0xffffffffu, l1, off);
    }
    float i0 = 1.0f / l0, i1 = 1.0f / l1;
#pragma unroll
    for (int nb = 0; nb < 8; nb++) {
        int col = h * DH + nb * 8 + 2 * fc;
        *(float2*)&g_ao[(size_t)(b * NN + row0g) * DIM + col] =
            make_float2(tf32f(O[nb][0] * i0), tf32f(O[nb][1] * i0));
        *(float2*)&g_ao[(size_t)(b * NN + row1g) * DIM + col] =
            make_float2(tf32f(O[nb][2] * i1), tf32f(O[nb][3] * i1));
    }
}

// ---------------- launch -----------------------------------------------------
extern "C" void kernel_launch(void* const* d_in, const int* in_sizes, int n_in,
                              void* d_out, int out_size) {
    const float* x = (const float*)d_in[0];
    const float* norm_g = (const float*)d_in[1];
    const float* norm_b = (const float*)d_in[2];
    const float* Wq = (const float*)d_in[3];
    const float* Wkv = (const float*)d_in[4];
    const float* q_scale = (const float*)d_in[5];
    const float* k_scale = (const float*)d_in[6];
    const float* null_kv = (const float*)d_in[7];
    const float* Wout = (const float*)d_in[8];
    float* out = (float*)d_out;

    float *p_xt, *p_xn, *p_wqt, *p_wkvt, *p_wot, *p_qraw, *p_kvraw, *p_ao;
    cudaGetSymbolAddress((void**)&p_xt, g_xt);
    cudaGetSymbolAddress((void**)&p_xn, g_xn);
    cudaGetSymbolAddress((void**)&p_wqt, g_wqt);
    cudaGetSymbolAddress((void**)&p_wkvt, g_wkvt);
    cudaGetSymbolAddress((void**)&p_wot, g_wot);
    cudaGetSymbolAddress((void**)&p_qraw, g_qraw);
    cudaGetSymbolAddress((void**)&p_kvraw, g_kvraw);
    cudaGetSymbolAddress((void**)&p_ao, g_ao);

    static int smem_set = 0;
    if (!smem_set) {
        cudaFuncSetAttribute(tf32gemm, cudaFuncAttributeMaxDynamicSharedMemorySize,
                             GEMM_SMEM_BYTES);
        smem_set = 1;
    }

    const int M = MM;

    // pre-round operands to tf32 in gmem
    tfconv_kernel<<<(M * DIM / 4) / 256, 256>>>(x, p_xt);
    tfconv_kernel<<<(DIM * DIM / 4) / 256, 256>>>(Wq, p_wqt);
    tfconv_kernel<<<(DIM * 2 * DIM / 4) / 256, 256>>>(Wkv, p_wkvt);
    tfconv_kernel<<<(DIM * DIM / 4) / 256, 256>>>(Wout, p_wot);
    ln_kernel<<<M, 256>>>(x, norm_g, norm_b);

    // projections (cvt-free mainloop)
    tf32gemm<<<dim3(2 * DIM / TBN, M / TBM), 256, GEMM_SMEM_BYTES>>>(
        p_xt, p_wkvt, p_kvraw, M, 2 * DIM, DIM);
    tf32gemm<<<dim3(DIM / TBN, M / TBM), 256, GEMM_SMEM_BYTES>>>(
        p_xn, p_wqt, p_qraw, M, DIM, DIM);

    // preps
    qprep_kernel<<<(BB * NN * HH) / 4, 128>>>(q_scale);
    kvprep_kernel<<<(BB * NN * HH) / 4, 128>>>(k_scale);
    nullprep_kernel<<<1, HH * NNUL * 32>>>(null_kv, k_scale);

    // attention
    attn_mma_kernel<<<dim3(NN / 64, HH, BB), 128, ATTN_SMEM>>>();

    // output projection
    tf32gemm<<<dim3(DIM / TBN, M / TBM), 256, GEMM_SMEM_BYTES>>>(
        p_ao, p_wot, out, M, DIM, DIM);
}

// round 9
// speedup vs baseline: 1.4232x; 1.1685x over previous
#include <cuda_runtime.h>
#include <cuda_bf16.h>
#include <math.h>
#include <stdint.h>

#define BB 2
#define NN 2048
#define DIM 1024
#define HH 16
#define DH 64
#define NNUL 2
#define JJ (NN + NNUL)
#define JJP 2112              // padded key rows; pad stays zero (static init)
#define SCALE 8.0f
#define LN_EPS 1e-5f
#define MM (BB * NN)

typedef __nv_bfloat16 bf16;

// ---------------- scratch ----------------------------------------------------
__device__ float g_xt[(size_t)MM * DIM];          // x tf32-rounded
__device__ float g_xn[(size_t)MM * DIM];          // LN(x) tf32-rounded
__device__ float g_wqt[(size_t)DIM * DIM];
__device__ float g_wkvt[(size_t)DIM * 2 * DIM];
__device__ float g_wot[(size_t)DIM * DIM];
__device__ float g_qraw[(size_t)MM * DIM];
__device__ float g_kvraw[(size_t)MM * 2 * DIM];
__device__ float g_q[(size_t)BB * HH * NN * DH];
__device__ float g_ao[(size_t)MM * DIM];
// attention operands, pre-converted bf16 hi/lo (pad rows/cols zero)
__device__ bf16 g_kh[(size_t)BB * HH * JJP * DH];
__device__ bf16 g_kl[(size_t)BB * HH * JJP * DH];
__device__ bf16 g_vth[(size_t)BB * HH * DH * JJP];   // V^T: [dh][key]
__device__ bf16 g_vtl[(size_t)BB * HH * DH * JJP];

__device__ __forceinline__ uint32_t to_tf32(float f) {
    uint32_t u;
    asm("cvt.rna.tf32.f32 %0, %1;" : "=r"(u) : "f"(f));
    return u;
}
__device__ __forceinline__ float tf32f(float f) { return __uint_as_float(to_tf32(f)); }

// ---------------- elementwise tf32 pre-round --------------------------------
__global__ void tfconv_kernel(const float* __restrict__ src, float* __restrict__ dst) {
    size_t i = ((size_t)blockIdx.x * 256 + threadIdx.x) * 4;
    float4 v = *(const float4*)&src[i];
    v.x = tf32f(v.x); v.y = tf32f(v.y); v.z = tf32f(v.z); v.w = tf32f(v.w);
    *(float4*)&dst[i] = v;
}

// ---------------- LayerNorm (tf32 out) ---------------------------------------
__global__ void ln_kernel(const float* __restrict__ x, const float* __restrict__ gma,
                          const float* __restrict__ bta) {
    int row = blockIdx.x;
    const float* xr = x + (size_t)row * DIM;
    float vals[4];
    float s = 0.f, ss = 0.f;
#pragma unroll
    for (int i = 0; i < 4; i++) {
        float v = xr[threadIdx.x + i * 256];
        vals[i] = v;
        s += v;
        ss += v * v;
    }
#pragma unroll
    for (int off = 16; off; off >>= 1) {
        s += __shfl_xor_sync(0xffffffffu, s, off);
        ss += __shfl_xor_sync(0xffffffffu, ss, off);
    }
    __shared__ float rs[8], rss[8];
    int w = threadIdx.x >> 5;
    if ((threadIdx.x & 31) == 0) { rs[w] = s; rss[w] = ss; }
    __syncthreads();
    if (threadIdx.x < 32) {
        float a = (threadIdx.x < 8) ? rs[threadIdx.x] : 0.f;
        float b2 = (threadIdx.x < 8) ? rss[threadIdx.x] : 0.f;
#pragma unroll
        for (int off = 4; off; off >>= 1) {
            a += __shfl_xor_sync(0xffffffffu, a, off);
            b2 += __shfl_xor_sync(0xffffffffu, b2, off);
        }
        if (threadIdx.x == 0) { rs[0] = a; rss[0] = b2; }
    }
    __syncthreads();
    float mu = rs[0] * (1.0f / DIM);
    float var = rss[0] * (1.0f / DIM) - mu * mu;
    float inv = rsqrtf(var + LN_EPS);
#pragma unroll
    for (int i = 0; i < 4; i++) {
        int d = threadIdx.x + i * 256;
        g_xn[(size_t)row * DIM + d] = tf32f((vals[i] - mu) * inv * gma[d] + bta[d]);
    }
}

// ---------------- TF32 GEMM (pre-rounded operands) ---------------------------
#define TBM 128
#define TBN 128
#define TBK 32
#define AS_STRIDE 36
#define BS_STRIDE 136
#define AS_FLOATS (TBM * AS_STRIDE)
#define BS_FLOATS (TBK * BS_STRIDE)
#define STAGE_FLOATS (AS_FLOATS + BS_FLOATS)
#define GEMM_SMEM_BYTES (2 * STAGE_FLOATS * 4)

__device__ __forceinline__ void cp_async16(void* sdst, const void* gsrc) {
    uint32_t sa = (uint32_t)__cvta_generic_to_shared(sdst);
    asm volatile("cp.async.cg.shared.global [%0], [%1], 16;\n" :: "r"(sa), "l"(gsrc));
}
__device__ __forceinline__ void cp_commit() {
    asm volatile("cp.async.commit_group;\n" ::: "memory");
}
__device__ __forceinline__ void cp_wait0() {
    asm volatile("cp.async.wait_group 0;\n" ::: "memory");
}

__global__ void __launch_bounds__(256)
tf32gemm(const float* __restrict__ A, const float* __restrict__ B,
         float* __restrict__ C, int M, int N, int K) {
    extern __shared__ float smem[];
    int tid = threadIdx.x;
    int lane = tid & 31;
    int warp = tid >> 5;
    int wm = warp >> 2;
    int wn = warp & 3;
    int row0 = blockIdx.y * TBM;
    int col0 = blockIdx.x * TBN;

    float acc[4][4][4];
#pragma unroll
    for (int i = 0; i < 4; i++)
#pragma unroll
        for (int j = 0; j < 4; j++)
#pragma unroll
            for (int r = 0; r < 4; r++) acc[i][j][r] = 0.f;

    int a_m = tid >> 3;
    int a_k4 = (tid & 7) * 4;
    int b_k = tid >> 5;
    int b_n4 = (tid & 31) * 4;
    int tiles = K / TBK;

    {
        float* As = smem;
        float* Bs = smem + AS_FLOATS;
#pragma unroll
        for (int t = 0; t < 4; t++) {
            int m = a_m + t * 32;
            cp_async16(&As[m * AS_STRIDE + a_k4], &A[(size_t)(row0 + m) * K + a_k4]);
        }
#pragma unroll
        for (int t = 0; t < 4; t++) {
            int k = b_k + t * 8;
            cp_async16(&Bs[k * BS_STRIDE + b_n4], &B[(size_t)k * N + col0 + b_n4]);
        }
        cp_commit();
    }

    for (int kt = 0; kt < tiles; kt++) {
        cp_wait0();
        __syncthreads();
        if (kt + 1 < tiles) {
            float* As = smem + ((kt + 1) & 1) * STAGE_FLOATS;
            float* Bs = As + AS_FLOATS;
            int kg = (kt + 1) * TBK;
#pragma unroll
            for (int t = 0; t < 4; t++) {
                int m = a_m + t * 32;
                cp_async16(&As[m * AS_STRIDE + a_k4], &A[(size_t)(row0 + m) * K + kg + a_k4]);
            }
#pragma unroll
            for (int t = 0; t < 4; t++) {
                int k = b_k + t * 8;
                cp_async16(&Bs[k * BS_STRIDE + b_n4], &B[(size_t)(kg + k) * N + col0 + b_n4]);
            }
            cp_commit();
        }
        const uint32_t* As = (const uint32_t*)(smem + (kt & 1) * STAGE_FLOATS);
        const uint32_t* Bs = As + AS_FLOATS;
        int fr = lane >> 2;
        int fc = lane & 3;
#pragma unroll
        for (int ks = 0; ks < 4; ks++) {
            int kb = ks * 8;
            uint32_t af[4][4], bf[4][2];
#pragma unroll
            for (int mt = 0; mt < 4; mt++) {
                int mb = wm * 64 + mt * 16;
                af[mt][0] = As[(mb + fr) * AS_STRIDE + kb + fc];
                af[mt][1] = As[(mb + 8 + fr) * AS_STRIDE + kb + fc];
                af[mt][2] = As[(mb + fr) * AS_STRIDE + kb + 4 + fc];
                af[mt][3] = As[(mb + 8 + fr) * AS_STRIDE + kb + 4 + fc];
            }
#pragma unroll
            for (int nt = 0; nt < 4; nt++) {
                int nb = wn * 32 + nt * 8;
                bf[nt][0] = Bs[(kb + fc) * BS_STRIDE + nb + fr];
                bf[nt][1] = Bs[(kb + 4 + fc) * BS_STRIDE + nb + fr];
            }
#pragma unroll
            for (int mt = 0; mt < 4; mt++)
#pragma unroll
                for (int nt = 0; nt < 4; nt++) {
                    asm volatile(
                        "mma.sync.aligned.m16n8k8.row.col.f32.tf32.tf32.f32 "
                        "{%0,%1,%2,%3}, {%4,%5,%6,%7}, {%8,%9}, {%0,%1,%2,%3};"
                        : "+f"(acc[mt][nt][0]), "+f"(acc[mt][nt][1]),
                          "+f"(acc[mt][nt][2]), "+f"(acc[mt][nt][3])
                        : "r"(af[mt][0]), "r"(af[mt][1]), "r"(af[mt][2]), "r"(af[mt][3]),
                          "r"(bf[nt][0]), "r"(bf[nt][1]));
                }
        }
        __syncthreads();
    }

    int fr = lane >> 2;
    int fc = lane & 3;
#pragma unroll
    for (int mt = 0; mt < 4; mt++) {
        int row = row0 + wm * 64 + mt * 16 + fr;
#pragma unroll
        for (int nt = 0; nt < 4; nt++) {
            int col = col0 + wn * 32 + nt * 8 + fc * 2;
            *(float2*)&C[(size_t)row * N + col] = make_float2(acc[mt][nt][0], acc[mt][nt][1]);
            *(float2*)&C[(size_t)(row + 8) * N + col] = make_float2(acc[mt][nt][2], acc[mt][nt][3]);
        }
    }
}

// ---------------- preps ------------------------------------------------------
__global__ void qprep_kernel(const float* __restrict__ qs) {
    int gw = blockIdx.x * 4 + (threadIdx.x >> 5);
    int lane = threadIdx.x & 31;
    int h = gw % HH;
    int n = (gw / HH) % NN;
    int b = gw / (HH * NN);
    const float* src = g_qraw + (size_t)(b * NN + n) * DIM + h * DH;
    float v0 = src[lane], v1 = src[lane + 32];
    float ss = v0 * v0 + v1 * v1;
#pragma unroll
    for (int off = 16; off; off >>= 1) ss += __shfl_xor_sync(0xffffffffu, ss, off);
    float inv = 1.0f / fmaxf(sqrtf(ss), 1e-12f);
    float* dst = g_q + (size_t)((b * HH + h) * NN + n) * DH;
    dst[lane] = v0 * inv * qs[lane];
    dst[lane + 32] = v1 * inv * qs[lane + 32];
}

// kvprep: k l2norm*scale -> bf16 hi/lo [b,h,j,dh]; v -> bf16 hi/lo V^T [b,h,dh,j]
__global__ void kvprep_kernel(const float* __restrict__ ks) {
    int gw = blockIdx.x * 4 + (threadIdx.x >> 5);
    int lane = threadIdx.x & 31;
    int h = gw % HH;
    int n = (gw / HH) % NN;
    int b = gw / (HH * NN);
    const float* row = g_kvraw + (size_t)(b * NN + n) * (2 * DIM);
    float k0 = row[h * DH + lane], k1 = row[h * DH + lane + 32];
    float v0 = row[DIM + h * DH + lane], v1 = row[DIM + h * DH + lane + 32];
    float ss = k0 * k0 + k1 * k1;
#pragma unroll
    for (int off = 16; off; off >>= 1) ss += __shfl_xor_sync(0xffffffffu, ss, off);
    float inv = 1.0f / fmaxf(sqrtf(ss), 1e-12f);
    k0 = k0 * inv * ks[lane];
    k1 = k1 * inv * ks[lane + 32];
    int j = n + NNUL;
    size_t kb = ((size_t)(b * HH + h) * JJP + j) * DH;
    bf16 h0 = __float2bfloat16_rn(k0);
    bf16 h1 = __float2bfloat16_rn(k1);
    g_kh[kb + lane] = h0;
    g_kh[kb + lane + 32] = h1;
    g_kl[kb + lane] = __float2bfloat16_rn(k0 - __bfloat162float(h0));
    g_kl[kb + lane + 32] = __float2bfloat16_rn(k1 - __bfloat162float(h1));
    size_t vb = (size_t)(b * HH + h) * DH * JJP;
    bf16 vh0 = __float2bfloat16_rn(v0);
    bf16 vh1 = __float2bfloat16_rn(v1);
    g_vth[vb + (size_t)lane * JJP + j] = vh0;
    g_vth[vb + (size_t)(lane + 32) * JJP + j] = vh1;
    g_vtl[vb + (size_t)lane * JJP + j] = __float2bfloat16_rn(v0 - __bfloat162float(vh0));
    g_vtl[vb + (size_t)(lane + 32) * JJP + j] = __float2bfloat16_rn(v1 - __bfloat162float(vh1));
}

__global__ void nullprep_kernel(const float* __restrict__ null_kv,
                                const float* __restrict__ ks) {
    int w = threadIdx.x >> 5;
    int lane = threadIdx.x & 31;
    int h = w / NNUL;
    int t = w % NNUL;
    const float* base = null_kv + (size_t)h * (2 * NNUL) * DH;
    float k0 = base[(2 * t) * DH + lane];
    float k1 = base[(2 * t) * DH + lane + 32];
    float v0 = base[(2 * t + 1) * DH + lane];
    float v1 = base[(2 * t + 1) * DH + lane + 32];
    float ss = k0 * k0 + k1 * k1;
#pragma unroll
    for (int off = 16; off; off >>= 1) ss += __shfl_xor_sync(0xffffffffu, ss, off);
    float inv = 1.0f / fmaxf(sqrtf(ss), 1e-12f);
    k0 = k0 * inv * ks[lane];
    k1 = k1 * inv * ks[lane + 32];
    bf16 kh0 = __float2bfloat16_rn(k0), kh1 = __float2bfloat16_rn(k1);
    bf16 kl0 = __float2bfloat16_rn(k0 - __bfloat162float(kh0));
    bf16 kl1 = __float2bfloat16_rn(k1 - __bfloat162float(kh1));
    bf16 vh0 = __float2bfloat16_rn(v0), vh1 = __float2bfloat16_rn(v1);
    bf16 vl0 = __float2bfloat16_rn(v0 - __bfloat162float(vh0));
    bf16 vl1 = __float2bfloat16_rn(v1 - __bfloat162float(vh1));
    for (int b = 0; b < BB; b++) {
        size_t kb = ((size_t)(b * HH + h) * JJP + t) * DH;
        g_kh[kb + lane] = kh0;
        g_kh[kb + lane + 32] = kh1;
        g_kl[kb + lane] = kl0;
        g_kl[kb + lane + 32] = kl1;
        size_t vb = (size_t)(b * HH + h) * DH * JJP;
        g_vth[vb + (size_t)lane * JJP + t] = vh0;
        g_vth[vb + (size_t)(lane + 32) * JJP + t] = vh1;
        g_vtl[vb + (size_t)lane * JJP + t] = vl0;
        g_vtl[vb + (size_t)(lane + 32) * JJP + t] = vl1;
    }
}

// ---------------- mma attention (cp.async staging, no in-loop convert) -------
#define KSTR 72
#define QSTR 68
#define TILE_HB (64 * KSTR * 2)        // 9216 bytes per array
#define ATTN_SMEM (4 * TILE_HB)

#define MMA_BF16(C, A, B0, B1)                                              \
    asm volatile(                                                           \
        "mma.sync.aligned.m16n8k16.row.col.f32.bf16.bf16.f32 "              \
        "{%0,%1,%2,%3}, {%4,%5,%6,%7}, {%8,%9}, {%0,%1,%2,%3};"             \
        : "+f"(C[0]), "+f"(C[1]), "+f"(C[2]), "+f"(C[3])                    \
        : "r"(A[0]), "r"(A[1]), "r"(A[2]), "r"(A[3]), "r"(B0), "r"(B1))

__device__ __forceinline__ uint32_t pack_bf2(float a, float b) {
    __nv_bfloat162 t;
    t.x = __float2bfloat16_rn(a);
    t.y = __float2bfloat16_rn(b);
    return *(uint32_t*)&t;
}

__global__ void __launch_bounds__(128)
attn_mma_kernel() {
    extern __shared__ char sm[];
    bf16* Kh = (bf16*)sm;
    bf16* Kl = (bf16*)(sm + TILE_HB);
    bf16* Vh = (bf16*)(sm + 2 * TILE_HB);
    bf16* Vl = (bf16*)(sm + 3 * TILE_HB);
    float* Qs = (float*)sm;

    int b = blockIdx.z, h = blockIdx.y;
    int qt = (gridDim.x - 1) - blockIdx.x;
    int tid = threadIdx.x;
    int w = tid >> 5;
    int lane = tid & 31;
    int fr = lane >> 2;
    int fc = lane & 3;

    size_t qbase = (size_t)((b * HH + h) * NN + qt * 64) * DH;
    const char* kh_b = (const char*)(g_kh + (size_t)(b * HH + h) * JJP * DH);
    const char* kl_b = (const char*)(g_kl + (size_t)(b * HH + h) * JJP * DH);
    const char* vth_b = (const char*)(g_vth + (size_t)(b * HH + h) * DH * JJP);
    const char* vtl_b = (const char*)(g_vtl + (size_t)(b * HH + h) * DH * JJP);

    for (int i = tid; i < 64 * 16; i += 128) {
        int r = i >> 4, c4 = (i & 15) * 4;
        *(float4*)&Qs[r * QSTR + c4] = *(const float4*)&g_q[qbase + (size_t)r * DH + c4];
    }
    __syncthreads();

    uint32_t qh[4][4], ql[4][4];
#pragma unroll
    for (int kc = 0; kc < 4; kc++) {
        int lr = w * 16 + fr;
        int c = kc * 16 + 2 * fc;
#pragma unroll
        for (int p = 0; p < 4; p++) {
            int rr = lr + (p & 1) * 8;
            int cc = c + (p >> 1) * 8;
            float x0 = Qs[rr * QSTR + cc], x1 = Qs[rr * QSTR + cc + 1];
            float h0 = __bfloat162float(__float2bfloat16_rn(x0));
            float h1 = __bfloat162float(__float2bfloat16_rn(x1));
            qh[kc][p] = pack_bf2(h0, h1);
            ql[kc][p] = pack_bf2(x0 - h0, x1 - h1);
        }
    }

    float O[8][4];
#pragma unroll
    for (int nb = 0; nb < 8; nb++)
#pragma unroll
        for (int r = 0; r < 4; r++) O[nb][r] = 0.f;

    float slope = exp2f(-0.5f * (float)(h + 1));
    int row0g = qt * 64 + w * 16 + fr;
    int row1g = row0g + 8;
    int my0 = row0g + NNUL, my1 = row1g + NNUL;
    float m0 = -1e30f, m1 = -1e30f, l0 = 0.f, l1 = 0.f;

    int nkeys = min(qt * 64 + 64 + NNUL, JJ);

    for (int j0 = 0; j0 < nkeys; j0 += 64) {
        __syncthreads();   // previous tile consumed (and Qs overlay freed)
        // stage K (rows=keys) and V^T (rows=dh), 16B chunks; pad rows are zero
        for (int i = tid; i < 64 * 8; i += 128) {
            int r = i >> 3, c = i & 7;
            uint32_t doff = r * 144 + c * 16;
            cp_async16(sm + 0 * TILE_HB + doff, kh_b + (size_t)(j0 + r) * 128 + c * 16);
            cp_async16(sm + 1 * TILE_HB + doff, kl_b + (size_t)(j0 + r) * 128 + c * 16);
            cp_async16(sm + 2 * TILE_HB + doff, vth_b + (size_t)r * (JJP * 2) + j0 * 2 + c * 16);
            cp_async16(sm + 3 * TILE_HB + doff, vtl_b + (size_t)r * (JJP * 2) + j0 * 2 + c * 16);
        }
        cp_commit();
        cp_wait0();
        __syncthreads();

        float S[8][4];
#pragma unroll
        for (int nb = 0; nb < 8; nb++)
#pragma unroll
            for (int r = 0; r < 4; r++) S[nb][r] = 0.f;

#pragma unroll
        for (int kc = 0; kc < 4; kc++) {
#pragma unroll
            for (int nb = 0; nb < 8; nb++) {
                int krow = nb * 8 + fr;
                int kcol = kc * 16 + 2 * fc;
                uint32_t b0h = *(uint32_t*)&Kh[krow * KSTR + kcol];
                uint32_t b1h = *(uint32_t*)&Kh[krow * KSTR + kcol + 8];
                uint32_t b0l = *(uint32_t*)&Kl[krow * KSTR + kcol];
                uint32_t b1l = *(uint32_t*)&Kl[krow * KSTR + kcol + 8];
                MMA_BF16(S[nb], qh[kc], b0h, b1h);
                MMA_BF16(S[nb], qh[kc], b0l, b1l);
                MMA_BF16(S[nb], ql[kc], b0h, b1h);
            }
        }

        float mt0 = -1e30f, mt1 = -1e30f;
#pragma unroll
        for (int nb = 0; nb < 8; nb++) {
#pragma unroll
            for (int e = 0; e < 2; e++) {
                int col = j0 + nb * 8 + 2 * fc + e;
                float s0 = S[nb][e] * SCALE + slope * (float)(col - my0);
                if (col > my0) s0 = -1e30f;
                S[nb][e] = s0;
                mt0 = fmaxf(mt0, s0);
                float s1 = S[nb][2 + e] * SCALE + slope * (float)(col - my1);
                if (col > my1) s1 = -1e30f;
                S[nb][2 + e] = s1;
                mt1 = fmaxf(mt1, s1);
            }
        }
#pragma unroll
        for (int off = 1; off <= 2; off <<= 1) {
            mt0 = fmaxf(mt0, __shfl_xor_sync(0xffffffffu, mt0, off));
            mt1 = fmaxf(mt1, __shfl_xor_sync(0xffffffffu, mt1, off));
        }
        float mn0 = fmaxf(m0, mt0), mn1 = fmaxf(m1, mt1);
        float c0 = __expf(m0 - mn0), c1 = __expf(m1 - mn1);
        m0 = mn0; m1 = mn1;

        float ps0 = 0.f, ps1 = 0.f;
#pragma unroll
        for (int nb = 0; nb < 8; nb++) {
#pragma unroll
            for (int e = 0; e < 2; e++) {
                float p0 = __expf(S[nb][e] - m0);
                float p1 = __expf(S[nb][2 + e] - m1);
                S[nb][e] = p0; S[nb][2 + e] = p1;
                ps0 += p0; ps1 += p1;
            }
        }
        l0 = l0 * c0 + ps0;
        l1 = l1 * c1 + ps1;
#pragma unroll
        for (int nb = 0; nb < 8; nb++) {
            O[nb][0] *= c0; O[nb][1] *= c0;
            O[nb][2] *= c1; O[nb][3] *= c1;
        }

        uint32_t ph[4][4], pl[4][4];
#pragma unroll
        for (int kc = 0; kc < 4; kc++) {
#pragma unroll
            for (int p = 0; p < 4; p++) {
                float x0 = S[2 * kc + (p >> 1)][(p & 1) * 2 + 0];
                float x1 = S[2 * kc + (p >> 1)][(p & 1) * 2 + 1];
                float h0 = __bfloat162float(__float2bfloat16_rn(x0));
                float h1 = __bfloat162float(__float2bfloat16_rn(x1));
                ph[kc][p] = pack_bf2(h0, h1);
                pl[kc][p] = pack_bf2(x0 - h0, x1 - h1);
            }
        }

#pragma unroll
        for (int kc = 0; kc < 4; kc++) {
#pragma unroll
            for (int nb = 0; nb < 8; nb++) {
                int drow = nb * 8 + fr;
                int kcol = kc * 16 + 2 * fc;
                uint32_t b0h = *(uint32_t*)&Vh[drow * KSTR + kcol];
                uint32_t b1h = *(uint32_t*)&Vh[drow * KSTR + kcol + 8];
                uint32_t b0l = *(uint32_t*)&Vl[drow * KSTR + kcol];
                uint32_t b1l = *(uint32_t*)&Vl[drow * KSTR + kcol + 8];
                MMA_BF16(O[nb], ph[kc], b0h, b1h);
                MMA_BF16(O[nb], ph[kc], b0l, b1l);
                MMA_BF16(O[nb], pl[kc], b0h, b1h);
            }
        }
    }

#pragma unroll
    for (int off = 1; off <= 2; off <<= 1) {
        l0 += __shfl_xor_sync(0xffffffffu, l0, off);
        l1 += __shfl_xor_sync(0xffffffffu, l1, off);
    }
    float i0 = 1.0f / l0, i1 = 1.0f / l1;
#pragma unroll
    for (int nb = 0; nb < 8; nb++) {
        int col = h * DH + nb * 8 + 2 * fc;
        *(float2*)&g_ao[(size_t)(b * NN + row0g) * DIM + col] =
            make_float2(tf32f(O[nb][0] * i0), tf32f(O[nb][1] * i0));
        *(float2*)&g_ao[(size_t)(b * NN + row1g) * DIM + col] =
            make_float2(tf32f(O[nb][2] * i1), tf32f(O[nb][3] * i1));
    }
}

// ---------------- launch -----------------------------------------------------
extern "C" void kernel_launch(void* const* d_in, const int* in_sizes, int n_in,
                              void* d_out, int out_size) {
    const float* x = (const float*)d_in[0];
    const float* norm_g = (const float*)d_in[1];
    const float* norm_b = (const float*)d_in[2];
    const float* Wq = (const float*)d_in[3];
    const float* Wkv = (const float*)d_in[4];
    const float* q_scale = (const float*)d_in[5];
    const float* k_scale = (const float*)d_in[6];
    const float* null_kv = (const float*)d_in[7];
    const float* Wout = (const float*)d_in[8];
    float* out = (float*)d_out;

    float *p_xt, *p_xn, *p_wqt, *p_wkvt, *p_wot, *p_qraw, *p_kvraw, *p_ao;
    cudaGetSymbolAddress((void**)&p_xt, g_xt);
    cudaGetSymbolAddress((void**)&p_xn, g_xn);
    cudaGetSymbolAddress((void**)&p_wqt, g_wqt);
    cudaGetSymbolAddress((void**)&p_wkvt, g_wkvt);
    cudaGetSymbolAddress((void**)&p_wot, g_wot);
    cudaGetSymbolAddress((void**)&p_qraw, g_qraw);
    cudaGetSymbolAddress((void**)&p_kvraw, g_kvraw);
    cudaGetSymbolAddress((void**)&p_ao, g_ao);

    static int smem_set = 0;
    if (!smem_set) {
        cudaFuncSetAttribute(tf32gemm, cudaFuncAttributeMaxDynamicSharedMemorySize,
                             GEMM_SMEM_BYTES);
        cudaFuncSetAttribute(attn_mma_kernel, cudaFuncAttributeMaxDynamicSharedMemorySize,
                             ATTN_SMEM);
        smem_set = 1;
    }

    const int M = MM;

    tfconv_kernel<<<(M * DIM / 4) / 256, 256>>>(x, p_xt);
    tfconv_kernel<<<(DIM * DIM / 4) / 256, 256>>>(Wq, p_wqt);
    tfconv_kernel<<<(DIM * 2 * DIM / 4) / 256, 256>>>(Wkv, p_wkvt);
    tfconv_kernel<<<(DIM * DIM / 4) / 256, 256>>>(Wout, p_wot);
    ln_kernel<<<M, 256>>>(x, norm_g, norm_b);

    tf32gemm<<<dim3(2 * DIM / TBN, M / TBM), 256, GEMM_SMEM_BYTES>>>(
        p_xt, p_wkvt, p_kvraw, M, 2 * DIM, DIM);
    tf32gemm<<<dim3(DIM / TBN, M / TBM), 256, GEMM_SMEM_BYTES>>>(
        p_xn, p_wqt, p_qraw, M, DIM, DIM);

    qprep_kernel<<<(BB * NN * HH) / 4, 128>>>(q_scale);
    kvprep_kernel<<<(BB * NN * HH) / 4, 128>>>(k_scale);
    nullprep_kernel<<<1, HH * NNUL * 32>>>(null_kv, k_scale);

    attn_mma_kernel<<<dim3(NN / 64, HH, BB), 128, ATTN_SMEM>>>();

    tf32gemm<<<dim3(DIM / TBN, M / TBM), 256, GEMM_SMEM_BYTES>>>(
        p_ao, p_wot, out, M, DIM, DIM);
}

// round 10
// speedup vs baseline: 1.4521x; 1.0203x over previous
#include <cuda_runtime.h>
#include <cuda_bf16.h>
#include <math.h>
#include <stdint.h>

#define BB 2
#define NN 2048
#define DIM 1024
#define HH 16
#define DH 64
#define NNUL 2
#define JJ (NN + NNUL)
#define JJP 2112
#define SCALE 8.0f
#define LN_EPS 1e-5f
#define MM (BB * NN)

typedef __nv_bfloat16 bf16;

// ---------------- scratch ----------------------------------------------------
__device__ float g_xt[(size_t)MM * DIM];
__device__ float g_xn[(size_t)MM * DIM];
__device__ float g_wqt[(size_t)DIM * DIM];
__device__ float g_wkvt[(size_t)DIM * 2 * DIM];
__device__ float g_wot[(size_t)DIM * DIM];
__device__ float g_qraw[(size_t)MM * DIM];
__device__ float g_kvraw[(size_t)MM * 2 * DIM];
__device__ float g_q[(size_t)BB * HH * NN * DH];
__device__ float g_ao[(size_t)MM * DIM];
__device__ bf16 g_kh[(size_t)BB * HH * JJP * DH];
__device__ bf16 g_kl[(size_t)BB * HH * JJP * DH];
__device__ bf16 g_vth[(size_t)BB * HH * DH * JJP];
__device__ bf16 g_vtl[(size_t)BB * HH * DH * JJP];

__device__ __forceinline__ uint32_t to_tf32(float f) {
    uint32_t u;
    asm("cvt.rna.tf32.f32 %0, %1;" : "=r"(u) : "f"(f));
    return u;
}
__device__ __forceinline__ float tf32f(float f) { return __uint_as_float(to_tf32(f)); }

// ---------------- elementwise tf32 pre-round (weights) ------------------------
__global__ void tfconv_kernel(const float* __restrict__ src, float* __restrict__ dst) {
    size_t i = ((size_t)blockIdx.x * 256 + threadIdx.x) * 4;
    float4 v = *(const float4*)&src[i];
    v.x = tf32f(v.x); v.y = tf32f(v.y); v.z = tf32f(v.z); v.w = tf32f(v.w);
    *(float4*)&dst[i] = v;
}

// ---------------- LayerNorm (emits tf32 xn AND tf32 x) ------------------------
__global__ void ln_kernel(const float* __restrict__ x, const float* __restrict__ gma,
                          const float* __restrict__ bta) {
    int row = blockIdx.x;
    const float* xr = x + (size_t)row * DIM;
    float vals[4];
    float s = 0.f, ss = 0.f;
#pragma unroll
    for (int i = 0; i < 4; i++) {
        float v = xr[threadIdx.x + i * 256];
        vals[i] = v;
        s += v;
        ss += v * v;
    }
#pragma unroll
    for (int off = 16; off; off >>= 1) {
        s += __shfl_xor_sync(0xffffffffu, s, off);
        ss += __shfl_xor_sync(0xffffffffu, ss, off);
    }
    __shared__ float rs[8], rss[8];
    int w = threadIdx.x >> 5;
    if ((threadIdx.x & 31) == 0) { rs[w] = s; rss[w] = ss; }
    __syncthreads();
    if (threadIdx.x < 32) {
        float a = (threadIdx.x < 8) ? rs[threadIdx.x] : 0.f;
        float b2 = (threadIdx.x < 8) ? rss[threadIdx.x] : 0.f;
#pragma unroll
        for (int off = 4; off; off >>= 1) {
            a += __shfl_xor_sync(0xffffffffu, a, off);
            b2 += __shfl_xor_sync(0xffffffffu, b2, off);
        }
        if (threadIdx.x == 0) { rs[0] = a; rss[0] = b2; }
    }
    __syncthreads();
    float mu = rs[0] * (1.0f / DIM);
    float var = rss[0] * (1.0f / DIM) - mu * mu;
    float inv = rsqrtf(var + LN_EPS);
#pragma unroll
    for (int i = 0; i < 4; i++) {
        int d = threadIdx.x + i * 256;
        g_xt[(size_t)row * DIM + d] = tf32f(vals[i]);
        g_xn[(size_t)row * DIM + d] = tf32f((vals[i] - mu) * inv * gma[d] + bta[d]);
    }
}

// ---------------- TF32 GEMM (pre-rounded operands, 2 CTAs/SM) -----------------
#define TBM 128
#define TBN 128
#define TBK 32
#define AS_STRIDE 36
#define BS_STRIDE 136
#define AS_FLOATS (TBM * AS_STRIDE)
#define BS_FLOATS (TBK * BS_STRIDE)
#define STAGE_FLOATS (AS_FLOATS + BS_FLOATS)
#define GEMM_SMEM_BYTES (2 * STAGE_FLOATS * 4)

__device__ __forceinline__ void cp_async16(void* sdst, const void* gsrc) {
    uint32_t sa = (uint32_t)__cvta_generic_to_shared(sdst);
    asm volatile("cp.async.cg.shared.global [%0], [%1], 16;\n" :: "r"(sa), "l"(gsrc));
}
__device__ __forceinline__ void cp_commit() {
    asm volatile("cp.async.commit_group;\n" ::: "memory");
}
__device__ __forceinline__ void cp_wait0() {
    asm volatile("cp.async.wait_group 0;\n" ::: "memory");
}

__global__ void __launch_bounds__(256, 2)
tf32gemm(const float* __restrict__ A, const float* __restrict__ B,
         float* __restrict__ C, int M, int N, int K) {
    extern __shared__ float smem[];
    int tid = threadIdx.x;
    int lane = tid & 31;
    int warp = tid >> 5;
    int wm = warp >> 2;
    int wn = warp & 3;
    int row0 = blockIdx.y * TBM;
    int col0 = blockIdx.x * TBN;

    float acc[4][4][4];
#pragma unroll
    for (int i = 0; i < 4; i++)
#pragma unroll
        for (int j = 0; j < 4; j++)
#pragma unroll
            for (int r = 0; r < 4; r++) acc[i][j][r] = 0.f;

    int a_m = tid >> 3;
    int a_k4 = (tid & 7) * 4;
    int b_k = tid >> 5;
    int b_n4 = (tid & 31) * 4;
    int tiles = K / TBK;

    {
        float* As = smem;
        float* Bs = smem + AS_FLOATS;
#pragma unroll
        for (int t = 0; t < 4; t++) {
            int m = a_m + t * 32;
            cp_async16(&As[m * AS_STRIDE + a_k4], &A[(size_t)(row0 + m) * K + a_k4]);
        }
#pragma unroll
        for (int t = 0; t < 4; t++) {
            int k = b_k + t * 8;
            cp_async16(&Bs[k * BS_STRIDE + b_n4], &B[(size_t)k * N + col0 + b_n4]);
        }
        cp_commit();
    }

    for (int kt = 0; kt < tiles; kt++) {
        cp_wait0();
        __syncthreads();
        if (kt + 1 < tiles) {
            float* As = smem + ((kt + 1) & 1) * STAGE_FLOATS;
            float* Bs = As + AS_FLOATS;
            int kg = (kt + 1) * TBK;
#pragma unroll
            for (int t = 0; t < 4; t++) {
                int m = a_m + t * 32;
                cp_async16(&As[m * AS_STRIDE + a_k4], &A[(size_t)(row0 + m) * K + kg + a_k4]);
            }
#pragma unroll
            for (int t = 0; t < 4; t++) {
                int k = b_k + t * 8;
                cp_async16(&Bs[k * BS_STRIDE + b_n4], &B[(size_t)(kg + k) * N + col0 + b_n4]);
            }
            cp_commit();
        }
        const uint32_t* As = (const uint32_t*)(smem + (kt & 1) * STAGE_FLOATS);
        const uint32_t* Bs = As + AS_FLOATS;
        int fr = lane >> 2;
        int fc = lane & 3;
#pragma unroll
        for (int ks = 0; ks < 4; ks++) {
            int kb = ks * 8;
            uint32_t af[4][4], bf[4][2];
#pragma unroll
            for (int mt = 0; mt < 4; mt++) {
                int mb = wm * 64 + mt * 16;
                af[mt][0] = As[(mb + fr) * AS_STRIDE + kb + fc];
                af[mt][1] = As[(mb + 8 + fr) * AS_STRIDE + kb + fc];
                af[mt][2] = As[(mb + fr) * AS_STRIDE + kb + 4 + fc];
                af[mt][3] = As[(mb + 8 + fr) * AS_STRIDE + kb + 4 + fc];
            }
#pragma unroll
            for (int nt = 0; nt < 4; nt++) {
                int nb = wn * 32 + nt * 8;
                bf[nt][0] = Bs[(kb + fc) * BS_STRIDE + nb + fr];
                bf[nt][1] = Bs[(kb + 4 + fc) * BS_STRIDE + nb + fr];
            }
#pragma unroll
            for (int mt = 0; mt < 4; mt++)
#pragma unroll
                for (int nt = 0; nt < 4; nt++) {
                    asm volatile(
                        "mma.sync.aligned.m16n8k8.row.col.f32.tf32.tf32.f32 "
                        "{%0,%1,%2,%3}, {%4,%5,%6,%7}, {%8,%9}, {%0,%1,%2,%3};"
                        : "+f"(acc[mt][nt][0]), "+f"(acc[mt][nt][1]),
                          "+f"(acc[mt][nt][2]), "+f"(acc[mt][nt][3])
                        : "r"(af[mt][0]), "r"(af[mt][1]), "r"(af[mt][2]), "r"(af[mt][3]),
                          "r"(bf[nt][0]), "r"(bf[nt][1]));
                }
        }
        __syncthreads();
    }

    int fr = lane >> 2;
    int fc = lane & 3;
#pragma unroll
    for (int mt = 0; mt < 4; mt++) {
        int row = row0 + wm * 64 + mt * 16 + fr;
#pragma unroll
        for (int nt = 0; nt < 4; nt++) {
            int col = col0 + wn * 32 + nt * 8 + fc * 2;
            *(float2*)&C[(size_t)row * N + col] = make_float2(acc[mt][nt][0], acc[mt][nt][1]);
            *(float2*)&C[(size_t)(row + 8) * N + col] = make_float2(acc[mt][nt][2], acc[mt][nt][3]);
        }
    }
}

// ---------------- preps ------------------------------------------------------
__global__ void qprep_kernel(const float* __restrict__ qs) {
    int gw = blockIdx.x * 4 + (threadIdx.x >> 5);
    int lane = threadIdx.x & 31;
    int h = gw % HH;
    int n = (gw / HH) % NN;
    int b = gw / (HH * NN);
    const float* src = g_qraw + (size_t)(b * NN + n) * DIM + h * DH;
    float v0 = src[lane], v1 = src[lane + 32];
    float ss = v0 * v0 + v1 * v1;
#pragma unroll
    for (int off = 16; off; off >>= 1) ss += __shfl_xor_sync(0xffffffffu, ss, off);
    float inv = 1.0f / fmaxf(sqrtf(ss), 1e-12f);
    float* dst = g_q + (size_t)((b * HH + h) * NN + n) * DH;
    dst[lane] = v0 * inv * qs[lane];
    dst[lane + 32] = v1 * inv * qs[lane + 32];
}

__global__ void kvprep_kernel(const float* __restrict__ ks) {
    int gw = blockIdx.x * 4 + (threadIdx.x >> 5);
    int lane = threadIdx.x & 31;
    int h = gw % HH;
    int n = (gw / HH) % NN;
    int b = gw / (HH * NN);
    const float* row = g_kvraw + (size_t)(b * NN + n) * (2 * DIM);
    float k0 = row[h * DH + lane], k1 = row[h * DH + lane + 32];
    float v0 = row[DIM + h * DH + lane], v1 = row[DIM + h * DH + lane + 32];
    float ss = k0 * k0 + k1 * k1;
#pragma unroll
    for (int off = 16; off; off >>= 1) ss += __shfl_xor_sync(0xffffffffu, ss, off);
    float inv = 1.0f / fmaxf(sqrtf(ss), 1e-12f);
    k0 = k0 * inv * ks[lane];
    k1 = k1 * inv * ks[lane + 32];
    int j = n + NNUL;
    size_t kb = ((size_t)(b * HH + h) * JJP + j) * DH;
    bf16 h0 = __float2bfloat16_rn(k0);
    bf16 h1 = __float2bfloat16_rn(k1);
    g_kh[kb + lane] = h0;
    g_kh[kb + lane + 32] = h1;
    g_kl[kb + lane] = __float2bfloat16_rn(k0 - __bfloat162float(h0));
    g_kl[kb + lane + 32] = __float2bfloat16_rn(k1 - __bfloat162float(h1));
    size_t vb = (size_t)(b * HH + h) * DH * JJP;
    bf16 vh0 = __float2bfloat16_rn(v0);
    bf16 vh1 = __float2bfloat16_rn(v1);
    g_vth[vb + (size_t)lane * JJP + j] = vh0;
    g_vth[vb + (size_t)(lane + 32) * JJP + j] = vh1;
    g_vtl[vb + (size_t)lane * JJP + j] = __float2bfloat16_rn(v0 - __bfloat162float(vh0));
    g_vtl[vb + (size_t)(lane + 32) * JJP + j] = __float2bfloat16_rn(v1 - __bfloat162float(vh1));
}

__global__ void nullprep_kernel(const float* __restrict__ null_kv,
                                const float* __restrict__ ks) {
    int w = threadIdx.x >> 5;
    int lane = threadIdx.x & 31;
    int h = w / NNUL;
    int t = w % NNUL;
    const float* base = null_kv + (size_t)h * (2 * NNUL) * DH;
    float k0 = base[(2 * t) * DH + lane];
    float k1 = base[(2 * t) * DH + lane + 32];
    float v0 = base[(2 * t + 1) * DH + lane];
    float v1 = base[(2 * t + 1) * DH + lane + 32];
    float ss = k0 * k0 + k1 * k1;
#pragma unroll
    for (int off = 16; off; off >>= 1) ss += __shfl_xor_sync(0xffffffffu, ss, off);
    float inv = 1.0f / fmaxf(sqrtf(ss), 1e-12f);
    k0 = k0 * inv * ks[lane];
    k1 = k1 * inv * ks[lane + 32];
    bf16 kh0 = __float2bfloat16_rn(k0), kh1 = __float2bfloat16_rn(k1);
    bf16 kl0 = __float2bfloat16_rn(k0 - __bfloat162float(kh0));
    bf16 kl1 = __float2bfloat16_rn(k1 - __bfloat162float(kh1));
    bf16 vh0 = __float2bfloat16_rn(v0), vh1 = __float2bfloat16_rn(v1);
    bf16 vl0 = __float2bfloat16_rn(v0 - __bfloat162float(vh0));
    bf16 vl1 = __float2bfloat16_rn(v1 - __bfloat162float(vh1));
    for (int b = 0; b < BB; b++) {
        size_t kb = ((size_t)(b * HH + h) * JJP + t) * DH;
        g_kh[kb + lane] = kh0;
        g_kh[kb + lane + 32] = kh1;
        g_kl[kb + lane] = kl0;
        g_kl[kb + lane + 32] = kl1;
        size_t vb = (size_t)(b * HH + h) * DH * JJP;
        g_vth[vb + (size_t)lane * JJP + t] = vh0;
        g_vth[vb + (size_t)(lane + 32) * JJP + t] = vh1;
        g_vtl[vb + (size_t)lane * JJP + t] = vl0;
        g_vtl[vb + (size_t)(lane + 32) * JJP + t] = vl1;
    }
}

// ---------------- mma attention ----------------------------------------------
#define KSTR 72
#define QSTR 68
#define TILE_HB (64 * KSTR * 2)
#define ATTN_SMEM (4 * TILE_HB)

#define MMA_BF16(C, A, B0, B1)                                              \
    asm volatile(                                                           \
        "mma.sync.aligned.m16n8k16.row.col.f32.bf16.bf16.f32 "              \
        "{%0,%1,%2,%3}, {%4,%5,%6,%7}, {%8,%9}, {%0,%1,%2,%3};"             \
        : "+f"(C[0]), "+f"(C[1]), "+f"(C[2]), "+f"(C[3])                    \
        : "r"(A[0]), "r"(A[1]), "r"(A[2]), "r"(A[3]), "r"(B0), "r"(B1))

__device__ __forceinline__ uint32_t pack_bf2(float a, float b) {
    __nv_bfloat162 t;
    t.x = __float2bfloat16_rn(a);
    t.y = __float2bfloat16_rn(b);
    return *(uint32_t*)&t;
}

__global__ void __launch_bounds__(128)
attn_mma_kernel() {
    extern __shared__ char sm[];
    bf16* Kh = (bf16*)sm;
    bf16* Kl = (bf16*)(sm + TILE_HB);
    bf16* Vh = (bf16*)(sm + 2 * TILE_HB);
    bf16* Vl = (bf16*)(sm + 3 * TILE_HB);
    float* Qs = (float*)sm;

    int b = blockIdx.z, h = blockIdx.y;
    int qt = (gridDim.x - 1) - blockIdx.x;
    int tid = threadIdx.x;
    int w = tid >> 5;
    int lane = tid & 31;
    int fr = lane >> 2;
    int fc = lane & 3;

    size_t qbase = (size_t)((b * HH + h) * NN + qt * 64) * DH;
    const char* kh_b = (const char*)(g_kh + (size_t)(b * HH + h) * JJP * DH);
    const char* kl_b = (const char*)(g_kl + (size_t)(b * HH + h) * JJP * DH);
    const char* vth_b = (const char*)(g_vth + (size_t)(b * HH + h) * DH * JJP);
    const char* vtl_b = (const char*)(g_vtl + (size_t)(b * HH + h) * DH * JJP);

    for (int i = tid; i < 64 * 16; i += 128) {
        int r = i >> 4, c4 = (i & 15) * 4;
        *(float4*)&Qs[r * QSTR + c4] = *(const float4*)&g_q[qbase + (size_t)r * DH + c4];
    }
    __syncthreads();

    uint32_t qh[4][4], ql[4][4];
#pragma unroll
    for (int kc = 0; kc < 4; kc++) {
        int lr = w * 16 + fr;
        int c = kc * 16 + 2 * fc;
#pragma unroll
        for (int p = 0; p < 4; p++) {
            int rr = lr + (p & 1) * 8;
            int cc = c + (p >> 1) * 8;
            float x0 = Qs[rr * QSTR + cc], x1 = Qs[rr * QSTR + cc + 1];
            float h0 = __bfloat162float(__float2bfloat16_rn(x0));
            float h1 = __bfloat162float(__float2bfloat16_rn(x1));
            qh[kc][p] = pack_bf2(h0, h1);
            ql[kc][p] = pack_bf2(x0 - h0, x1 - h1);
        }
    }

    float O[8][4];
#pragma unroll
    for (int nb = 0; nb < 8; nb++)
#pragma unroll
        for (int r = 0; r < 4; r++) O[nb][r] = 0.f;

    float slope = exp2f(-0.5f * (float)(h + 1));
    int row0g = qt * 64 + w * 16 + fr;
    int row1g = row0g + 8;
    int my0 = row0g + NNUL, my1 = row1g + NNUL;
    float m0 = -1e30f, m1 = -1e30f, l0 = 0.f, l1 = 0.f;

    int nkeys = min(qt * 64 + 64 + NNUL, JJ);

    for (int j0 = 0; j0 < nkeys; j0 += 64) {
        __syncthreads();
        for (int i = tid; i < 64 * 8; i += 128) {
            int r = i >> 3, c = i & 7;
            uint32_t doff = r * 144 + c * 16;
            cp_async16(sm + 0 * TILE_HB + doff, kh_b + (size_t)(j0 + r) * 128 + c * 16);
            cp_async16(sm + 1 * TILE_HB + doff, kl_b + (size_t)(j0 + r) * 128 + c * 16);
            cp_async16(sm + 2 * TILE_HB + doff, vth_b + (size_t)r * (JJP * 2) + j0 * 2 + c * 16);
            cp_async16(sm + 3 * TILE_HB + doff, vtl_b + (size_t)r * (JJP * 2) + j0 * 2 + c * 16);
        }
        cp_commit();
        cp_wait0();
        __syncthreads();

        float S[8][4];
#pragma unroll
        for (int nb = 0; nb < 8; nb++)
#pragma unroll
            for (int r = 0; r < 4; r++) S[nb][r] = 0.f;

#pragma unroll
        for (int kc = 0; kc < 4; kc++) {
#pragma unroll
            for (int nb = 0; nb < 8; nb++) {
                int krow = nb * 8 + fr;
                int kcol = kc * 16 + 2 * fc;
                uint32_t b0h = *(uint32_t*)&Kh[krow * KSTR + kcol];
                uint32_t b1h = *(uint32_t*)&Kh[krow * KSTR + kcol + 8];
                uint32_t b0l = *(uint32_t*)&Kl[krow * KSTR + kcol];
                uint32_t b1l = *(uint32_t*)&Kl[krow * KSTR + kcol + 8];
                MMA_BF16(S[nb], qh[kc], b0h, b1h);
                MMA_BF16(S[nb], qh[kc], b0l, b1l);
                MMA_BF16(S[nb], ql[kc], b0h, b1h);
            }
        }

        float mt0 = -1e30f, mt1 = -1e30f;
#pragma unroll
        for (int nb = 0; nb < 8; nb++) {
#pragma unroll
            for (int e = 0; e < 2; e++) {
                int col = j0 + nb * 8 + 2 * fc + e;
                float s0 = S[nb][e] * SCALE + slope * (float)(col - my0);
                if (col > my0) s0 = -1e30f;
                S[nb][e] = s0;
                mt0 = fmaxf(mt0, s0);
                float s1 = S[nb][2 + e] * SCALE + slope * (float)(col - my1);
                if (col > my1) s1 = -1e30f;
                S[nb][2 + e] = s1;
                mt1 = fmaxf(mt1, s1);
            }
        }
#pragma unroll
        for (int off = 1; off <= 2; off <<= 1) {
            mt0 = fmaxf(mt0, __shfl_xor_sync(0xffffffffu, mt0, off));
            mt1 = fmaxf(mt1, __shfl_xor_sync(0xffffffffu, mt1, off));
        }
        float mn0 = fmaxf(m0, mt0), mn1 = fmaxf(m1, mt1);
        float c0 = __expf(m0 - mn0), c1 = __expf(m1 - mn1);
        m0 = mn0; m1 = mn1;

        float ps0 = 0.f, ps1 = 0.f;
#pragma unroll
        for (int nb = 0; nb < 8; nb++) {
#pragma unroll
            for (int e = 0; e < 2; e++) {
                float p0 = __expf(S[nb][e] - m0);
                float p1 = __expf(S[nb][2 + e] - m1);
                S[nb][e] = p0; S[nb][2 + e] = p1;
                ps0 += p0; ps1 += p1;
            }
        }
        l0 = l0 * c0 + ps0;
        l1 = l1 * c1 + ps1;
#pragma unroll
        for (int nb = 0; nb < 8; nb++) {
            O[nb][0] *= c0; O[nb][1] *= c0;
            O[nb][2] *= c1; O[nb][3] *= c1;
        }

        uint32_t ph[4][4], pl[4][4];
#pragma unroll
        for (int kc = 0; kc < 4; kc++) {
#pragma unroll
            for (int p = 0; p < 4; p++) {
                float x0 = S[2 * kc + (p >> 1)][(p & 1) * 2 + 0];
                float x1 = S[2 * kc + (p >> 1)][(p & 1) * 2 + 1];
                float h0 = __bfloat162float(__float2bfloat16_rn(x0));
                float h1 = __bfloat162float(__float2bfloat16_rn(x1));
                ph[kc][p] = pack_bf2(h0, h1);
                pl[kc][p] = pack_bf2(x0 - h0, x1 - h1);
            }
        }

#pragma unroll
        for (int kc = 0; kc < 4; kc++) {
#pragma unroll
            for (int nb = 0; nb < 8; nb++) {
                int drow = nb * 8 + fr;
                int kcol = kc * 16 + 2 * fc;
                uint32_t b0h = *(uint32_t*)&Vh[drow * KSTR + kcol];
                uint32_t b1h = *(uint32_t*)&Vh[drow * KSTR + kcol + 8];
                uint32_t b0l = *(uint32_t*)&Vl[drow * KSTR + kcol];
                uint32_t b1l = *(uint32_t*)&Vl[drow * KSTR + kcol + 8];
                MMA_BF16(O[nb], ph[kc], b0h, b1h);
                MMA_BF16(O[nb], ph[kc], b0l, b1l);
                MMA_BF16(O[nb], pl[kc], b0h, b1h);
            }
        }
    }

#pragma unroll
    for (int off = 1; off <= 2; off <<= 1) {
        l0 += __shfl_xor_sync(0xffffffffu, l0, off);
        l1 += __shfl_xor_sync(0xffffffffu, l1, off);
    }
    float i0 = 1.0f / l0, i1 = 1.0f / l1;
#pragma unroll
    for (int nb = 0; nb < 8; nb++) {
        int col = h * DH + nb * 8 + 2 * fc;
        *(float2*)&g_ao[(size_t)(b * NN + row0g) * DIM + col] =
            make_float2(tf32f(O[nb][0] * i0), tf32f(O[nb][1] * i0));
        *(float2*)&g_ao[(size_t)(b * NN + row1g) * DIM + col] =
            make_float2(tf32f(O[nb][2] * i1), tf32f(O[nb][3] * i1));
    }
}

// ---------------- launch -----------------------------------------------------
extern "C" void kernel_launch(void* const* d_in, const int* in_sizes, int n_in,
                              void* d_out, int out_size) {
    const float* x = (const float*)d_in[0];
    const float* norm_g = (const float*)d_in[1];
    const float* norm_b = (const float*)d_in[2];
    const float* Wq = (const float*)d_in[3];
    const float* Wkv = (const float*)d_in[4];
    const float* q_scale = (const float*)d_in[5];
    const float* k_scale = (const float*)d_in[6];
    const float* null_kv = (const float*)d_in[7];
    const float* Wout = (const float*)d_in[8];
    float* out = (float*)d_out;

    float *p_xt, *p_xn, *p_wqt, *p_wkvt, *p_wot, *p_qraw, *p_kvraw, *p_ao;
    cudaGetSymbolAddress((void**)&p_xt, g_xt);
    cudaGetSymbolAddress((void**)&p_xn, g_xn);
    cudaGetSymbolAddress((void**)&p_wqt, g_wqt);
    cudaGetSymbolAddress((void**)&p_wkvt, g_wkvt);
    cudaGetSymbolAddress((void**)&p_wot, g_wot);
    cudaGetSymbolAddress((void**)&p_qraw, g_qraw);
    cudaGetSymbolAddress((void**)&p_kvraw, g_kvraw);
    cudaGetSymbolAddress((void**)&p_ao, g_ao);

    static int smem_set = 0;
    if (!smem_set) {
        cudaFuncSetAttribute(tf32gemm, cudaFuncAttributeMaxDynamicSharedMemorySize,
                             GEMM_SMEM_BYTES);
        cudaFuncSetAttribute(attn_mma_kernel, cudaFuncAttributeMaxDynamicSharedMemorySize,
                             ATTN_SMEM);
        smem_set = 1;
    }

    const int M = MM;

    // 1-4: LN (emits xt + xn) and weight pre-rounds
    ln_kernel<<<M, 256>>>(x, norm_g, norm_b);
    tfconv_kernel<<<(DIM * 2 * DIM / 4) / 256, 256>>>(Wkv, p_wkvt);
    tfconv_kernel<<<(DIM * DIM / 4) / 256, 256>>>(Wq, p_wqt);
    tfconv_kernel<<<(DIM * DIM / 4) / 256, 256>>>(Wout, p_wot);

    // 5-6: projections (launch 6 = Q gemm lands in the ncu sample slot)
    tf32gemm<<<dim3(2 * DIM / TBN, M / TBM), 256, GEMM_SMEM_BYTES>>>(
        p_xt, p_wkvt, p_kvraw, M, 2 * DIM, DIM);
    tf32gemm<<<dim3(DIM / TBN, M / TBM), 256, GEMM_SMEM_BYTES>>>(
        p_xn, p_wqt, p_qraw, M, DIM, DIM);

    // 7-9: preps
    qprep_kernel<<<(BB * NN * HH) / 4, 128>>>(q_scale);
    kvprep_kernel<<<(BB * NN * HH) / 4, 128>>>(k_scale);
    nullprep_kernel<<<1, HH * NNUL * 32>>>(null_kv, k_scale);

    // 10: attention
    attn_mma_kernel<<<dim3(NN / 64, HH, BB), 128, ATTN_SMEM>>>();

    // 11: output projection
    tf32gemm<<<dim3(DIM / TBN, M / TBM), 256, GEMM_SMEM_BYTES>>>(
        p_ao, p_wot, out, M, DIM, DIM);
}

// round 11
// speedup vs baseline: 1.4835x; 1.0216x over previous
#include <cuda_runtime.h>
#include <cuda_bf16.h>
#include <math.h>
#include <stdint.h>

#define BB 2
#define NN 2048
#define DIM 1024
#define HH 16
#define DH 64
#define NNUL 2
#define JJ (NN + NNUL)
#define JJP 2112
#define SCALE 8.0f
#define LN_EPS 1e-5f
#define MM (BB * NN)

typedef __nv_bfloat16 bf16;

// ---------------- scratch ----------------------------------------------------
__device__ float g_xt[(size_t)MM * DIM];
__device__ float g_xn[(size_t)MM * DIM];
__device__ float g_wqt[(size_t)DIM * DIM];
__device__ float g_wkvt[(size_t)DIM * 2 * DIM];
__device__ float g_wot[(size_t)DIM * DIM];
__device__ float g_qraw[(size_t)MM * DIM];
__device__ float g_kvraw[(size_t)MM * 2 * DIM];
__device__ float g_q[(size_t)BB * HH * NN * DH];
__device__ float g_ao[(size_t)MM * DIM];
__device__ bf16 g_kh[(size_t)BB * HH * JJP * DH];
__device__ bf16 g_kl[(size_t)BB * HH * JJP * DH];
__device__ bf16 g_vth[(size_t)BB * HH * DH * JJP];
__device__ bf16 g_vtl[(size_t)BB * HH * DH * JJP];

__device__ __forceinline__ uint32_t to_tf32(float f) {
    uint32_t u;
    asm("cvt.rna.tf32.f32 %0, %1;" : "=r"(u) : "f"(f));
    return u;
}
__device__ __forceinline__ float tf32f(float f) { return __uint_as_float(to_tf32(f)); }

// ---------------- elementwise tf32 pre-round (weights) ------------------------
__global__ void tfconv_kernel(const float* __restrict__ src, float* __restrict__ dst) {
    size_t i = ((size_t)blockIdx.x * 256 + threadIdx.x) * 4;
    float4 v = *(const float4*)&src[i];
    v.x = tf32f(v.x); v.y = tf32f(v.y); v.z = tf32f(v.z); v.w = tf32f(v.w);
    *(float4*)&dst[i] = v;
}

// ---------------- LayerNorm (emits tf32 xn AND tf32 x) ------------------------
__global__ void ln_kernel(const float* __restrict__ x, const float* __restrict__ gma,
                          const float* __restrict__ bta) {
    int row = blockIdx.x;
    const float* xr = x + (size_t)row * DIM;
    float vals[4];
    float s = 0.f, ss = 0.f;
#pragma unroll
    for (int i = 0; i < 4; i++) {
        float v = xr[threadIdx.x + i * 256];
        vals[i] = v;
        s += v;
        ss += v * v;
    }
#pragma unroll
    for (int off = 16; off; off >>= 1) {
        s += __shfl_xor_sync(0xffffffffu, s, off);
        ss += __shfl_xor_sync(0xffffffffu, ss, off);
    }
    __shared__ float rs[8], rss[8];
    int w = threadIdx.x >> 5;
    if ((threadIdx.x & 31) == 0) { rs[w] = s; rss[w] = ss; }
    __syncthreads();
    if (threadIdx.x < 32) {
        float a = (threadIdx.x < 8) ? rs[threadIdx.x] : 0.f;
        float b2 = (threadIdx.x < 8) ? rss[threadIdx.x] : 0.f;
#pragma unroll
        for (int off = 4; off; off >>= 1) {
            a += __shfl_xor_sync(0xffffffffu, a, off);
            b2 += __shfl_xor_sync(0xffffffffu, b2, off);
        }
        if (threadIdx.x == 0) { rs[0] = a; rss[0] = b2; }
    }
    __syncthreads();
    float mu = rs[0] * (1.0f / DIM);
    float var = rss[0] * (1.0f / DIM) - mu * mu;
    float inv = rsqrtf(var + LN_EPS);
#pragma unroll
    for (int i = 0; i < 4; i++) {
        int d = threadIdx.x + i * 256;
        g_xt[(size_t)row * DIM + d] = tf32f(vals[i]);
        g_xn[(size_t)row * DIM + d] = tf32f((vals[i] - mu) * inv * gma[d] + bta[d]);
    }
}

// ---------------- TF32 GEMM core (K = DIM fixed) ------------------------------
#define TBM 128
#define TBN 128
#define TBK 32
#define AS_STRIDE 36
#define BS_STRIDE 136
#define AS_FLOATS (TBM * AS_STRIDE)
#define BS_FLOATS (TBK * BS_STRIDE)
#define STAGE_FLOATS (AS_FLOATS + BS_FLOATS)
#define GEMM_SMEM_BYTES (2 * STAGE_FLOATS * 4)
#define GK DIM
#define GTILES (GK / TBK)

__device__ __forceinline__ void cp_async16(void* sdst, const void* gsrc) {
    uint32_t sa = (uint32_t)__cvta_generic_to_shared(sdst);
    asm volatile("cp.async.cg.shared.global [%0], [%1], 16;\n" :: "r"(sa), "l"(gsrc));
}
__device__ __forceinline__ void cp_commit() {
    asm volatile("cp.async.commit_group;\n" ::: "memory");
}
__device__ __forceinline__ void cp_wait0() {
    asm volatile("cp.async.wait_group 0;\n" ::: "memory");
}

__device__ __forceinline__ void gemm_body(const float* __restrict__ A,
                                          const float* __restrict__ B,
                                          float* __restrict__ C,
                                          int N, int row0, int col0, float* smem) {
    int tid = threadIdx.x;
    int lane = tid & 31;
    int warp = tid >> 5;
    int wm = warp >> 2;
    int wn = warp & 3;

    float acc[4][4][4];
#pragma unroll
    for (int i = 0; i < 4; i++)
#pragma unroll
        for (int j = 0; j < 4; j++)
#pragma unroll
            for (int r = 0; r < 4; r++) acc[i][j][r] = 0.f;

    int a_m = tid >> 3;
    int a_k4 = (tid & 7) * 4;
    int b_k = tid >> 5;
    int b_n4 = (tid & 31) * 4;

    {
        float* As = smem;
        float* Bs = smem + AS_FLOATS;
#pragma unroll
        for (int t = 0; t < 4; t++) {
            int m = a_m + t * 32;
            cp_async16(&As[m * AS_STRIDE + a_k4], &A[(size_t)(row0 + m) * GK + a_k4]);
        }
#pragma unroll
        for (int t = 0; t < 4; t++) {
            int k = b_k + t * 8;
            cp_async16(&Bs[k * BS_STRIDE + b_n4], &B[(size_t)k * N + col0 + b_n4]);
        }
        cp_commit();
    }

    for (int kt = 0; kt < GTILES; kt++) {
        cp_wait0();
        __syncthreads();   // loads(kt) visible AND all warps done with buffer kt%2
        if (kt + 1 < GTILES) {
            float* As = smem + ((kt + 1) & 1) * STAGE_FLOATS;
            float* Bs = As + AS_FLOATS;
            int kg = (kt + 1) * TBK;
#pragma unroll
            for (int t = 0; t < 4; t++) {
                int m = a_m + t * 32;
                cp_async16(&As[m * AS_STRIDE + a_k4], &A[(size_t)(row0 + m) * GK + kg + a_k4]);
            }
#pragma unroll
            for (int t = 0; t < 4; t++) {
                int k = b_k + t * 8;
                cp_async16(&Bs[k * BS_STRIDE + b_n4], &B[(size_t)(kg + k) * N + col0 + b_n4]);
            }
            cp_commit();
        }
        const uint32_t* As = (const uint32_t*)(smem + (kt & 1) * STAGE_FLOATS);
        const uint32_t* Bs = As + AS_FLOATS;
        int fr = lane >> 2;
        int fc = lane & 3;
#pragma unroll
        for (int ks = 0; ks < 4; ks++) {
            int kb = ks * 8;
            uint32_t af[4][4], bf[4][2];
#pragma unroll
            for (int mt = 0; mt < 4; mt++) {
                int mb = wm * 64 + mt * 16;
                af[mt][0] = As[(mb + fr) * AS_STRIDE + kb + fc];
                af[mt][1] = As[(mb + 8 + fr) * AS_STRIDE + kb + fc];
                af[mt][2] = As[(mb + fr) * AS_STRIDE + kb + 4 + fc];
                af[mt][3] = As[(mb + 8 + fr) * AS_STRIDE + kb + 4 + fc];
            }
#pragma unroll
            for (int nt = 0; nt < 4; nt++) {
                int nb = wn * 32 + nt * 8;
                bf[nt][0] = Bs[(kb + fc) * BS_STRIDE + nb + fr];
                bf[nt][1] = Bs[(kb + 4 + fc) * BS_STRIDE + nb + fr];
            }
#pragma unroll
            for (int mt = 0; mt < 4; mt++)
#pragma unroll
                for (int nt = 0; nt < 4; nt++) {
                    asm volatile(
                        "mma.sync.aligned.m16n8k8.row.col.f32.tf32.tf32.f32 "
                        "{%0,%1,%2,%3}, {%4,%5,%6,%7}, {%8,%9}, {%0,%1,%2,%3};"
                        : "+f"(acc[mt][nt][0]), "+f"(acc[mt][nt][1]),
                          "+f"(acc[mt][nt][2]), "+f"(acc[mt][nt][3])
                        : "r"(af[mt][0]), "r"(af[mt][1]), "r"(af[mt][2]), "r"(af[mt][3]),
                          "r"(bf[nt][0]), "r"(bf[nt][1]));
                }
        }
        // no trailing barrier: next iteration's (wait0 + sync) protects the buffer
    }

    int fr = lane >> 2;
    int fc = lane & 3;
#pragma unroll
    for (int mt = 0; mt < 4; mt++) {
        int row = row0 + wm * 64 + mt * 16 + fr;
#pragma unroll
        for (int nt = 0; nt < 4; nt++) {
            int col = col0 + wn * 32 + nt * 8 + fc * 2;
            *(float2*)&C[(size_t)row * N + col] = make_float2(acc[mt][nt][0], acc[mt][nt][1]);
            *(float2*)&C[(size_t)(row + 8) * N + col] = make_float2(acc[mt][nt][2], acc[mt][nt][3]);
        }
    }
}

// fused Q + KV projection: blockIdx.x in [0,8) -> xn@Wq ; [8,24) -> x@Wkv
__global__ void __launch_bounds__(256, 2)
tf32gemm_qkv() {
    extern __shared__ float smem[];
    const float* A;
    const float* B;
    float* C;
    int N, col0;
    if (blockIdx.x < 8) {
        A = g_xn; B = g_wqt; C = g_qraw; N = DIM; col0 = blockIdx.x * TBN;
    } else {
        A = g_xt; B = g_wkvt; C = g_kvraw; N = 2 * DIM; col0 = (blockIdx.x - 8) * TBN;
    }
    gemm_body(A, B, C, N, blockIdx.y * TBM, col0, smem);
}

// output projection
__global__ void __launch_bounds__(256, 2)
tf32gemm_o(float* __restrict__ out) {
    extern __shared__ float smem[];
    gemm_body(g_ao, g_wot, out, DIM, blockIdx.y * TBM, blockIdx.x * TBN, smem);
}

// ---------------- preps ------------------------------------------------------
__global__ void qprep_kernel(const float* __restrict__ qs) {
    int gw = blockIdx.x * 4 + (threadIdx.x >> 5);
    int lane = threadIdx.x & 31;
    int h = gw % HH;
    int n = (gw / HH) % NN;
    int b = gw / (HH * NN);
    const float* src = g_qraw + (size_t)(b * NN + n) * DIM + h * DH;
    float v0 = src[lane], v1 = src[lane + 32];
    float ss = v0 * v0 + v1 * v1;
#pragma unroll
    for (int off = 16; off; off >>= 1) ss += __shfl_xor_sync(0xffffffffu, ss, off);
    float inv = 1.0f / fmaxf(sqrtf(ss), 1e-12f);
    float* dst = g_q + (size_t)((b * HH + h) * NN + n) * DH;
    dst[lane] = v0 * inv * qs[lane];
    dst[lane + 32] = v1 * inv * qs[lane + 32];
}

__global__ void kvprep_kernel(const float* __restrict__ ks) {
    int gw = blockIdx.x * 4 + (threadIdx.x >> 5);
    int lane = threadIdx.x & 31;
    int h = gw % HH;
    int n = (gw / HH) % NN;
    int b = gw / (HH * NN);
    const float* row = g_kvraw + (size_t)(b * NN + n) * (2 * DIM);
    float k0 = row[h * DH + lane], k1 = row[h * DH + lane + 32];
    float v0 = row[DIM + h * DH + lane], v1 = row[DIM + h * DH + lane + 32];
    float ss = k0 * k0 + k1 * k1;
#pragma unroll
    for (int off = 16; off; off >>= 1) ss += __shfl_xor_sync(0xffffffffu, ss, off);
    float inv = 1.0f / fmaxf(sqrtf(ss), 1e-12f);
    k0 = k0 * inv * ks[lane];
    k1 = k1 * inv * ks[lane + 32];
    int j = n + NNUL;
    size_t kb = ((size_t)(b * HH + h) * JJP + j) * DH;
    bf16 h0 = __float2bfloat16_rn(k0);
    bf16 h1 = __float2bfloat16_rn(k1);
    g_kh[kb + lane] = h0;
    g_kh[kb + lane + 32] = h1;
    g_kl[kb + lane] = __float2bfloat16_rn(k0 - __bfloat162float(h0));
    g_kl[kb + lane + 32] = __float2bfloat16_rn(k1 - __bfloat162float(h1));
    size_t vb = (size_t)(b * HH + h) * DH * JJP;
    bf16 vh0 = __float2bfloat16_rn(v0);
    bf16 vh1 = __float2bfloat16_rn(v1);
    g_vth[vb + (size_t)lane * JJP + j] = vh0;
    g_vth[vb + (size_t)(lane + 32) * JJP + j] = vh1;
    g_vtl[vb + (size_t)lane * JJP + j] = __float2bfloat16_rn(v0 - __bfloat162float(vh0));
    g_vtl[vb + (size_t)(lane + 32) * JJP + j] = __float2bfloat16_rn(v1 - __bfloat162float(vh1));
}

__global__ void nullprep_kernel(const float* __restrict__ null_kv,
                                const float* __restrict__ ks) {
    int w = threadIdx.x >> 5;
    int lane = threadIdx.x & 31;
    int h = w / NNUL;
    int t = w % NNUL;
    const float* base = null_kv + (size_t)h * (2 * NNUL) * DH;
    float k0 = base[(2 * t) * DH + lane];
    float k1 = base[(2 * t) * DH + lane + 32];
    float v0 = base[(2 * t + 1) * DH + lane];
    float v1 = base[(2 * t + 1) * DH + lane + 32];
    float ss = k0 * k0 + k1 * k1;
#pragma unroll
    for (int off = 16; off; off >>= 1) ss += __shfl_xor_sync(0xffffffffu, ss, off);
    float inv = 1.0f / fmaxf(sqrtf(ss), 1e-12f);
    k0 = k0 * inv * ks[lane];
    k1 = k1 * inv * ks[lane + 32];
    bf16 kh0 = __float2bfloat16_rn(k0), kh1 = __float2bfloat16_rn(k1);
    bf16 kl0 = __float2bfloat16_rn(k0 - __bfloat162float(kh0));
    bf16 kl1 = __float2bfloat16_rn(k1 - __bfloat162float(kh1));
    bf16 vh0 = __float2bfloat16_rn(v0), vh1 = __float2bfloat16_rn(v1);
    bf16 vl0 = __float2bfloat16_rn(v0 - __bfloat162float(vh0));
    bf16 vl1 = __float2bfloat16_rn(v1 - __bfloat162float(vh1));
    for (int b = 0; b < BB; b++) {
        size_t kb = ((size_t)(b * HH + h) * JJP + t) * DH;
        g_kh[kb + lane] = kh0;
        g_kh[kb + lane + 32] = kh1;
        g_kl[kb + lane] = kl0;
        g_kl[kb + lane + 32] = kl1;
        size_t vb = (size_t)(b * HH + h) * DH * JJP;
        g_vth[vb + (size_t)lane * JJP + t] = vh0;
        g_vth[vb + (size_t)(lane + 32) * JJP + t] = vh1;
        g_vtl[vb + (size_t)lane * JJP + t] = vl0;
        g_vtl[vb + (size_t)(lane + 32) * JJP + t] = vl1;
    }
}

// ---------------- mma attention ----------------------------------------------
#define KSTR 72
#define QSTR 68
#define TILE_HB (64 * KSTR * 2)
#define ATTN_SMEM (4 * TILE_HB)

#define MMA_BF16(C, A, B0, B1)                                              \
    asm volatile(                                                           \
        "mma.sync.aligned.m16n8k16.row.col.f32.bf16.bf16.f32 "              \
        "{%0,%1,%2,%3}, {%4,%5,%6,%7}, {%8,%9}, {%0,%1,%2,%3};"             \
        : "+f"(C[0]), "+f"(C[1]), "+f"(C[2]), "+f"(C[3])                    \
        : "r"(A[0]), "r"(A[1]), "r"(A[2]), "r"(A[3]), "r"(B0), "r"(B1))

__device__ __forceinline__ uint32_t pack_bf2(float a, float b) {
    __nv_bfloat162 t;
    t.x = __float2bfloat16_rn(a);
    t.y = __float2bfloat16_rn(b);
    return *(uint32_t*)&t;
}

__global__ void __launch_bounds__(128)
attn_mma_kernel() {
    extern __shared__ char sm[];
    bf16* Kh = (bf16*)sm;
    bf16* Kl = (bf16*)(sm + TILE_HB);
    bf16* Vh = (bf16*)(sm + 2 * TILE_HB);
    bf16* Vl = (bf16*)(sm + 3 * TILE_HB);
    float* Qs = (float*)sm;

    int b = blockIdx.z, h = blockIdx.y;
    int qt = (gridDim.x - 1) - blockIdx.x;
    int tid = threadIdx.x;
    int w = tid >> 5;
    int lane = tid & 31;
    int fr = lane >> 2;
    int fc = lane & 3;

    size_t qbase = (size_t)((b * HH + h) * NN + qt * 64) * DH;
    const char* kh_b = (const char*)(g_kh + (size_t)(b * HH + h) * JJP * DH);
    const char* kl_b = (const char*)(g_kl + (size_t)(b * HH + h) * JJP * DH);
    const char* vth_b = (const char*)(g_vth + (size_t)(b * HH + h) * DH * JJP);
    const char* vtl_b = (const char*)(g_vtl + (size_t)(b * HH + h) * DH * JJP);

    for (int i = tid; i < 64 * 16; i += 128) {
        int r = i >> 4, c4 = (i & 15) * 4;
        *(float4*)&Qs[r * QSTR + c4] = *(const float4*)&g_q[qbase + (size_t)r * DH + c4];
    }
    __syncthreads();

    uint32_t qh[4][4], ql[4][4];
#pragma unroll
    for (int kc = 0; kc < 4; kc++) {
        int lr = w * 16 + fr;
        int c = kc * 16 + 2 * fc;
#pragma unroll
        for (int p = 0; p < 4; p++) {
            int rr = lr + (p & 1) * 8;
            int cc = c + (p >> 1) * 8;
            float x0 = Qs[rr * QSTR + cc], x1 = Qs[rr * QSTR + cc + 1];
            float h0 = __bfloat162float(__float2bfloat16_rn(x0));
            float h1 = __bfloat162float(__float2bfloat16_rn(x1));
            qh[kc][p] = pack_bf2(h0, h1);
            ql[kc][p] = pack_bf2(x0 - h0, x1 - h1);
        }
    }

    float O[8][4];
#pragma unroll
    for (int nb = 0; nb < 8; nb++)
#pragma unroll
        for (int r = 0; r < 4; r++) O[nb][r] = 0.f;

    float slope = exp2f(-0.5f * (float)(h + 1));
    int row0g = qt * 64 + w * 16 + fr;
    int row1g = row0g + 8;
    int my0 = row0g + NNUL, my1 = row1g + NNUL;
    float m0 = -1e30f, m1 = -1e30f, l0 = 0.f, l1 = 0.f;

    int nkeys = min(qt * 64 + 64 + NNUL, JJ);

    for (int j0 = 0; j0 < nkeys; j0 += 64) {
        __syncthreads();
        for (int i = tid; i < 64 * 8; i += 128) {
            int r = i >> 3, c = i & 7;
            uint32_t doff = r * 144 + c * 16;
            cp_async16(sm + 0 * TILE_HB + doff, kh_b + (size_t)(j0 + r) * 128 + c * 16);
            cp_async16(sm + 1 * TILE_HB + doff, kl_b + (size_t)(j0 + r) * 128 + c * 16);
            cp_async16(sm + 2 * TILE_HB + doff, vth_b + (size_t)r * (JJP * 2) + j0 * 2 + c * 16);
            cp_async16(sm + 3 * TILE_HB + doff, vtl_b + (size_t)r * (JJP * 2) + j0 * 2 + c * 16);
        }
        cp_commit();
        cp_wait0();
        __syncthreads();

        float S[8][4];
#pragma unroll
        for (int nb = 0; nb < 8; nb++)
#pragma unroll
            for (int r = 0; r < 4; r++) S[nb][r] = 0.f;

#pragma unroll
        for (int kc = 0; kc < 4; kc++) {
#pragma unroll
            for (int nb = 0; nb < 8; nb++) {
                int krow = nb * 8 + fr;
                int kcol = kc * 16 + 2 * fc;
                uint32_t b0h = *(uint32_t*)&Kh[krow * KSTR + kcol];
                uint32_t b1h = *(uint32_t*)&Kh[krow * KSTR + kcol + 8];
                uint32_t b0l = *(uint32_t*)&Kl[krow * KSTR + kcol];
                uint32_t b1l = *(uint32_t*)&Kl[krow * KSTR + kcol + 8];
                MMA_BF16(S[nb], qh[kc], b0h, b1h);
                MMA_BF16(S[nb], qh[kc], b0l, b1l);
                MMA_BF16(S[nb], ql[kc], b0h, b1h);
            }
        }

        float mt0 = -1e30f, mt1 = -1e30f;
#pragma unroll
        for (int nb = 0; nb < 8; nb++) {
#pragma unroll
            for (int e = 0; e < 2; e++) {
                int col = j0 + nb * 8 + 2 * fc + e;
                float s0 = S[nb][e] * SCALE + slope * (float)(col - my0);
                if (col > my0) s0 = -1e30f;
                S[nb][e] = s0;
                mt0 = fmaxf(mt0, s0);
                float s1 = S[nb][2 + e] * SCALE + slope * (float)(col - my1);
                if (col > my1) s1 = -1e30f;
                S[nb][2 + e] = s1;
                mt1 = fmaxf(mt1, s1);
            }
        }
#pragma unroll
        for (int off = 1; off <= 2; off <<= 1) {
            mt0 = fmaxf(mt0, __shfl_xor_sync(0xffffffffu, mt0, off));
            mt1 = fmaxf(mt1, __shfl_xor_sync(0xffffffffu, mt1, off));
        }
        float mn0 = fmaxf(m0, mt0), mn1 = fmaxf(m1, mt1);
        float c0 = __expf(m0 - mn0), c1 = __expf(m1 - mn1);
        m0 = mn0; m1 = mn1;

        float ps0 = 0.f, ps1 = 0.f;
#pragma unroll
        for (int nb = 0; nb < 8; nb++) {
#pragma unroll
            for (int e = 0; e < 2; e++) {
                float p0 = __expf(S[nb][e] - m0);
                float p1 = __expf(S[nb][2 + e] - m1);
                S[nb][e] = p0; S[nb][2 + e] = p1;
                ps0 += p0; ps1 += p1;
            }
        }
        l0 = l0 * c0 + ps0;
        l1 = l1 * c1 + ps1;
#pragma unroll
        for (int nb = 0; nb < 8; nb++) {
            O[nb][0] *= c0; O[nb][1] *= c0;
            O[nb][2] *= c1; O[nb][3] *= c1;
        }

        uint32_t ph[4][4], pl[4][4];
#pragma unroll
        for (int kc = 0; kc < 4; kc++) {
#pragma unroll
            for (int p = 0; p < 4; p++) {
                float x0 = S[2 * kc + (p >> 1)][(p & 1) * 2 + 0];
                float x1 = S[2 * kc + (p >> 1)][(p & 1) * 2 + 1];
                float h0 = __bfloat162float(__float2bfloat16_rn(x0));
                float h1 = __bfloat162float(__float2bfloat16_rn(x1));
                ph[kc][p] = pack_bf2(h0, h1);
                pl[kc][p] = pack_bf2(x0 - h0, x1 - h1);
            }
        }

#pragma unroll
        for (int kc = 0; kc < 4; kc++) {
#pragma unroll
            for (int nb = 0; nb < 8; nb++) {
                int drow = nb * 8 + fr;
                int kcol = kc * 16 + 2 * fc;
                uint32_t b0h = *(uint32_t*)&Vh[drow * KSTR + kcol];
                uint32_t b1h = *(uint32_t*)&Vh[drow * KSTR + kcol + 8];
                uint32_t b0l = *(uint32_t*)&Vl[drow * KSTR + kcol];
                uint32_t b1l = *(uint32_t*)&Vl[drow * KSTR + kcol + 8];
                MMA_BF16(O[nb], ph[kc], b0h, b1h);
                MMA_BF16(O[nb], ph[kc], b0l, b1l);
                MMA_BF16(O[nb], pl[kc], b0h, b1h);
            }
        }
    }

#pragma unroll
    for (int off = 1; off <= 2; off <<= 1) {
        l0 += __shfl_xor_sync(0xffffffffu, l0, off);
        l1 += __shfl_xor_sync(0xffffffffu, l1, off);
    }
    float i0 = 1.0f / l0, i1 = 1.0f / l1;
#pragma unroll
    for (int nb = 0; nb < 8; nb++) {
        int col = h * DH + nb * 8 + 2 * fc;
        *(float2*)&g_ao[(size_t)(b * NN + row0g) * DIM + col] =
            make_float2(tf32f(O[nb][0] * i0), tf32f(O[nb][1] * i0));
        *(float2*)&g_ao[(size_t)(b * NN + row1g) * DIM + col] =
            make_float2(tf32f(O[nb][2] * i1), tf32f(O[nb][3] * i1));
    }
}

// ---------------- launch -----------------------------------------------------
extern "C" void kernel_launch(void* const* d_in, const int* in_sizes, int n_in,
                              void* d_out, int out_size) {
    const float* x = (const float*)d_in[0];
    const float* norm_g = (const float*)d_in[1];
    const float* norm_b = (const float*)d_in[2];
    const float* Wq = (const float*)d_in[3];
    const float* Wkv = (const float*)d_in[4];
    const float* q_scale = (const float*)d_in[5];
    const float* k_scale = (const float*)d_in[6];
    const float* null_kv = (const float*)d_in[7];
    const float* Wout = (const float*)d_in[8];
    float* out = (float*)d_out;

    float *p_wqt, *p_wkvt, *p_wot;
    cudaGetSymbolAddress((void**)&p_wqt, g_wqt);
    cudaGetSymbolAddress((void**)&p_wkvt, g_wkvt);
    cudaGetSymbolAddress((void**)&p_wot, g_wot);

    static int smem_set = 0;
    if (!smem_set) {
        cudaFuncSetAttribute(tf32gemm_qkv, cudaFuncAttributeMaxDynamicSharedMemorySize,
                             GEMM_SMEM_BYTES);
        cudaFuncSetAttribute(tf32gemm_o, cudaFuncAttributeMaxDynamicSharedMemorySize,
                             GEMM_SMEM_BYTES);
        cudaFuncSetAttribute(attn_mma_kernel, cudaFuncAttributeMaxDynamicSharedMemorySize,
                             ATTN_SMEM);
        smem_set = 1;
    }

    // 1-3: weight pre-rounds + LN (launch 4 = fused QKV gemm for ncu capture)
    tfconv_kernel<<<(DIM * DIM / 4) / 256, 256>>>(Wq, p_wqt);
    tfconv_kernel<<<(DIM * 2 * DIM / 4) / 256, 256>>>(Wkv, p_wkvt);
    ln_kernel<<<MM, 256>>>(x, norm_g, norm_b);

    // 4: fused Q + KV projections (768 CTAs, one wave-packed launch)
    tf32gemm_qkv<<<dim3(24, MM / TBM), 256, GEMM_SMEM_BYTES>>>();

    // 5: Wout pre-round (independent, overlaps preps)
    tfconv_kernel<<<(DIM * DIM / 4) / 256, 256>>>(Wout, p_wot);

    // 6-8: preps
    qprep_kernel<<<(BB * NN * HH) / 4, 128>>>(q_scale);
    kvprep_kernel<<<(BB * NN * HH) / 4, 128>>>(k_scale);
    nullprep_kernel<<<1, HH * NNUL * 32>>>(null_kv, k_scale);

    // 9: attention
    attn_mma_kernel<<<dim3(NN / 64, HH, BB), 128, ATTN_SMEM>>>();

    // 10: output projection
    tf32gemm_o<<<dim3(DIM / TBN, MM / TBM), 256, GEMM_SMEM_BYTES>>>(out);
}

// round 12
// speedup vs baseline: 1.5326x; 1.0331x over previous
#include <cuda_runtime.h>
#include <cuda_bf16.h>
#include <math.h>
#include <stdint.h>

#define BB 2
#define NN 2048
#define DIM 1024
#define HH 16
#define DH 64
#define NNUL 2
#define JJ (NN + NNUL)
#define JJP 2112
#define SCALE 8.0f
#define LN_EPS 1e-5f
#define MM (BB * NN)

typedef __nv_bfloat16 bf16;

// ---------------- scratch ----------------------------------------------------
__device__ float g_xt[(size_t)MM * DIM];
__device__ float g_xn[(size_t)MM * DIM];
__device__ float g_wqt[(size_t)DIM * DIM];        // transposed [N][K], tf32
__device__ float g_wkvt[(size_t)2 * DIM * DIM];   // transposed [N][K], tf32
__device__ float g_wot[(size_t)DIM * DIM];        // transposed [N][K], tf32
__device__ float g_qraw[(size_t)MM * DIM];
__device__ float g_kvraw[(size_t)MM * 2 * DIM];
__device__ float g_q[(size_t)BB * HH * NN * DH];
__device__ float g_ao[(size_t)MM * DIM];
__device__ bf16 g_kh[(size_t)BB * HH * JJP * DH];
__device__ bf16 g_kl[(size_t)BB * HH * JJP * DH];
__device__ bf16 g_vth[(size_t)BB * HH * DH * JJP];
__device__ bf16 g_vtl[(size_t)BB * HH * DH * JJP];

__device__ __forceinline__ uint32_t to_tf32(float f) {
    uint32_t u;
    asm("cvt.rna.tf32.f32 %0, %1;" : "=r"(u) : "f"(f));
    return u;
}
__device__ __forceinline__ float tf32f(float f) { return __uint_as_float(to_tf32(f)); }

// ---------------- weight transpose + tf32 round: [K][N] -> [N][K] -------------
__global__ void wtconv_kernel(const float* __restrict__ W, float* __restrict__ Wt,
                              int K, int N) {
    __shared__ float t[32][33];
    int tx = threadIdx.x, ty = threadIdx.y;
    int n0 = blockIdx.x * 32, k0 = blockIdx.y * 32;
#pragma unroll
    for (int e = 0; e < 4; e++)
        t[ty + 8 * e][tx] = W[(size_t)(k0 + ty + 8 * e) * N + n0 + tx];
    __syncthreads();
#pragma unroll
    for (int e = 0; e < 4; e++) {
        float v = t[tx][ty + 8 * e];
        int n = n0 + ty + 8 * e, k = k0 + tx;
        Wt[(size_t)n * K + k] = tf32f(v);
    }
}

// ---------------- LayerNorm (emits tf32 xn AND tf32 x) ------------------------
__global__ void ln_kernel(const float* __restrict__ x, const float* __restrict__ gma,
                          const float* __restrict__ bta) {
    int row = blockIdx.x;
    const float* xr = x + (size_t)row * DIM;
    float vals[4];
    float s = 0.f, ss = 0.f;
#pragma unroll
    for (int i = 0; i < 4; i++) {
        float v = xr[threadIdx.x + i * 256];
        vals[i] = v;
        s += v;
        ss += v * v;
    }
#pragma unroll
    for (int off = 16; off; off >>= 1) {
        s += __shfl_xor_sync(0xffffffffu, s, off);
        ss += __shfl_xor_sync(0xffffffffu, ss, off);
    }
    __shared__ float rs[8], rss[8];
    int w = threadIdx.x >> 5;
    if ((threadIdx.x & 31) == 0) { rs[w] = s; rss[w] = ss; }
    __syncthreads();
    if (threadIdx.x < 32) {
        float a = (threadIdx.x < 8) ? rs[threadIdx.x] : 0.f;
        float b2 = (threadIdx.x < 8) ? rss[threadIdx.x] : 0.f;
#pragma unroll
        for (int off = 4; off; off >>= 1) {
            a += __shfl_xor_sync(0xffffffffu, a, off);
            b2 += __shfl_xor_sync(0xffffffffu, b2, off);
        }
        if (threadIdx.x == 0) { rs[0] = a; rss[0] = b2; }
    }
    __syncthreads();
    float mu = rs[0] * (1.0f / DIM);
    float var = rss[0] * (1.0f / DIM) - mu * mu;
    float inv = rsqrtf(var + LN_EPS);
#pragma unroll
    for (int i = 0; i < 4; i++) {
        int d = threadIdx.x + i * 256;
        g_xt[(size_t)row * DIM + d] = tf32f(vals[i]);
        g_xn[(size_t)row * DIM + d] = tf32f((vals[i] - mu) * inv * gma[d] + bta[d]);
    }
}

// ---------------- TF32 GEMM core (K=DIM, B stored [N][K], ldmatrix frags) ----
#define TBM 128
#define TBN 128
#define TBK 32
#define TSTR 36                          // floats per row in smem tiles
#define TILE_FLOATS (128 * TSTR)         // 4608 per operand tile
#define STAGE_FLOATS (2 * TILE_FLOATS)   // A + B
#define GEMM_SMEM_BYTES (2 * STAGE_FLOATS * 4)
#define GK DIM
#define GTILES (GK / TBK)

__device__ __forceinline__ void cp_async16(void* sdst, const void* gsrc) {
    uint32_t sa = (uint32_t)__cvta_generic_to_shared(sdst);
    asm volatile("cp.async.cg.shared.global [%0], [%1], 16;\n" :: "r"(sa), "l"(gsrc));
}
__device__ __forceinline__ void cp_commit() {
    asm volatile("cp.async.commit_group;\n" ::: "memory");
}
__device__ __forceinline__ void cp_wait0() {
    asm volatile("cp.async.wait_group 0;\n" ::: "memory");
}
#define LDSM_X4(r0, r1, r2, r3, addr)                                        \
    asm volatile("ldmatrix.sync.aligned.m8n8.x4.shared.b16 {%0,%1,%2,%3}, [%4];" \
        : "=r"(r0), "=r"(r1), "=r"(r2), "=r"(r3) : "r"(addr))

__device__ __forceinline__ void gemm_body(const float* __restrict__ A,
                                          const float* __restrict__ Bt,
                                          float* __restrict__ C,
                                          int N, int row0, int col0, float* smem) {
    int tid = threadIdx.x;
    int lane = tid & 31;
    int warp = tid >> 5;
    int wm = warp >> 2;
    int wn = warp & 3;

    float acc[4][4][4];
#pragma unroll
    for (int i = 0; i < 4; i++)
#pragma unroll
        for (int j = 0; j < 4; j++)
#pragma unroll
            for (int r = 0; r < 4; r++) acc[i][j][r] = 0.f;

    // staging coords (identical for A and Bt: 128 rows x 32 k)
    int s_r = tid >> 3;             // 0..31 (+t*32)
    int s_c4 = (tid & 7) * 4;       // k offset

    uint32_t smem_u32 = (uint32_t)__cvta_generic_to_shared(smem);

    // ldmatrix per-thread base addresses (byte offsets within a stage)
    int ltile = lane >> 3;          // 0..3
    int lrow = lane & 7;
    // A: tile -> (rowoff = (ltile&1)*8, coloff = (ltile>>1)*4)
    uint32_t aBase[4];
#pragma unroll
    for (int mt = 0; mt < 4; mt++) {
        int r = wm * 64 + mt * 16 + (ltile & 1) * 8 + lrow;
        aBase[mt] = (uint32_t)((r * TSTR + (ltile >> 1) * 4) * 4);
    }
    // B: tile -> (rowoff = (ltile>>1)*8, coloff = (ltile&1)*4); pair p covers nt=2p,2p+1
    uint32_t bBase[2];
#pragma unroll
    for (int p = 0; p < 2; p++) {
        int r = wn * 32 + p * 16 + (ltile >> 1) * 8 + lrow;
        bBase[p] = (uint32_t)(TILE_FLOATS * 4 + (r * TSTR + (ltile & 1) * 4) * 4);
    }

    {
        float* As = smem;
        float* Bs = smem + TILE_FLOATS;
#pragma unroll
        for (int t = 0; t < 4; t++) {
            int r = s_r + t * 32;
            cp_async16(&As[r * TSTR + s_c4], &A[(size_t)(row0 + r) * GK + s_c4]);
            cp_async16(&Bs[r * TSTR + s_c4], &Bt[(size_t)(col0 + r) * GK + s_c4]);
        }
        cp_commit();
    }

    for (int kt = 0; kt < GTILES; kt++) {
        cp_wait0();
        __syncthreads();
        if (kt + 1 < GTILES) {
            float* As = smem + ((kt + 1) & 1) * STAGE_FLOATS;
            float* Bs = As + TILE_FLOATS;
            int kg = (kt + 1) * TBK;
#pragma unroll
            for (int t = 0; t < 4; t++) {
                int r = s_r + t * 32;
                cp_async16(&As[r * TSTR + s_c4], &A[(size_t)(row0 + r) * GK + kg + s_c4]);
                cp_async16(&Bs[r * TSTR + s_c4], &Bt[(size_t)(col0 + r) * GK + kg + s_c4]);
            }
            cp_commit();
        }
        uint32_t stage = smem_u32 + (uint32_t)((kt & 1) * STAGE_FLOATS * 4);
#pragma unroll
        for (int ks = 0; ks < 4; ks++) {
            uint32_t koff = (uint32_t)(ks * 8 * 4);   // 8 floats per ks
            uint32_t af[4][4], bf[4][2];
#pragma unroll
            for (int mt = 0; mt < 4; mt++)
                LDSM_X4(af[mt][0], af[mt][1], af[mt][2], af[mt][3],
                        stage + aBase[mt] + koff);
#pragma unroll
            for (int p = 0; p < 2; p++)
                LDSM_X4(bf[2 * p][0], bf[2 * p][1], bf[2 * p + 1][0], bf[2 * p + 1][1],
                        stage + bBase[p] + koff);
#pragma unroll
            for (int mt = 0; mt < 4; mt++)
#pragma unroll
                for (int nt = 0; nt < 4; nt++) {
                    asm volatile(
                        "mma.sync.aligned.m16n8k8.row.col.f32.tf32.tf32.f32 "
                        "{%0,%1,%2,%3}, {%4,%5,%6,%7}, {%8,%9}, {%0,%1,%2,%3};"
                        : "+f"(acc[mt][nt][0]), "+f"(acc[mt][nt][1]),
                          "+f"(acc[mt][nt][2]), "+f"(acc[mt][nt][3])
                        : "r"(af[mt][0]), "r"(af[mt][1]), "r"(af[mt][2]), "r"(af[mt][3]),
                          "r"(bf[nt][0]), "r"(bf[nt][1]));
                }
        }
    }

    int fr = lane >> 2;
    int fc = lane & 3;
#pragma unroll
    for (int mt = 0; mt < 4; mt++) {
        int row = row0 + wm * 64 + mt * 16 + fr;
#pragma unroll
        for (int nt = 0; nt < 4; nt++) {
            int col = col0 + wn * 32 + nt * 8 + fc * 2;
            *(float2*)&C[(size_t)row * N + col] = make_float2(acc[mt][nt][0], acc[mt][nt][1]);
            *(float2*)&C[(size_t)(row + 8) * N + col] = make_float2(acc[mt][nt][2], acc[mt][nt][3]);
        }
    }
}

// fused Q + KV projection: blockIdx.x in [0,8) -> xn@WqT ; [8,24) -> x@WkvT
__global__ void __launch_bounds__(256, 2)
tf32gemm_qkv() {
    extern __shared__ float smem[];
    const float* A;
    const float* B;
    float* C;
    int N, col0;
    if (blockIdx.x < 8) {
        A = g_xn; B = g_wqt; C = g_qraw; N = DIM; col0 = blockIdx.x * TBN;
    } else {
        A = g_xt; B = g_wkvt; C = g_kvraw; N = 2 * DIM; col0 = (blockIdx.x - 8) * TBN;
    }
    gemm_body(A, B, C, N, blockIdx.y * TBM, col0, smem);
}

__global__ void __launch_bounds__(256, 2)
tf32gemm_o(float* __restrict__ out) {
    extern __shared__ float smem[];
    gemm_body(g_ao, g_wot, out, DIM, blockIdx.y * TBM, blockIdx.x * TBN, smem);
}

// ---------------- preps ------------------------------------------------------
__global__ void qprep_kernel(const float* __restrict__ qs) {
    int gw = blockIdx.x * 4 + (threadIdx.x >> 5);
    int lane = threadIdx.x & 31;
    int h = gw % HH;
    int n = (gw / HH) % NN;
    int b = gw / (HH * NN);
    const float* src = g_qraw + (size_t)(b * NN + n) * DIM + h * DH;
    float v0 = src[lane], v1 = src[lane + 32];
    float ss = v0 * v0 + v1 * v1;
#pragma unroll
    for (int off = 16; off; off >>= 1) ss += __shfl_xor_sync(0xffffffffu, ss, off);
    float inv = 1.0f / fmaxf(sqrtf(ss), 1e-12f);
    float* dst = g_q + (size_t)((b * HH + h) * NN + n) * DH;
    dst[lane] = v0 * inv * qs[lane];
    dst[lane + 32] = v1 * inv * qs[lane + 32];
}

__global__ void kvprep_kernel(const float* __restrict__ ks) {
    int gw = blockIdx.x * 4 + (threadIdx.x >> 5);
    int lane = threadIdx.x & 31;
    int h = gw % HH;
    int n = (gw / HH) % NN;
    int b = gw / (HH * NN);
    const float* row = g_kvraw + (size_t)(b * NN + n) * (2 * DIM);
    float k0 = row[h * DH + lane], k1 = row[h * DH + lane + 32];
    float v0 = row[DIM + h * DH + lane], v1 = row[DIM + h * DH + lane + 32];
    float ss = k0 * k0 + k1 * k1;
#pragma unroll
    for (int off = 16; off; off >>= 1) ss += __shfl_xor_sync(0xffffffffu, ss, off);
    float inv = 1.0f / fmaxf(sqrtf(ss), 1e-12f);
    k0 = k0 * inv * ks[lane];
    k1 = k1 * inv * ks[lane + 32];
    int j = n + NNUL;
    size_t kb = ((size_t)(b * HH + h) * JJP + j) * DH;
    bf16 h0 = __float2bfloat16_rn(k0);
    bf16 h1 = __float2bfloat16_rn(k1);
    g_kh[kb + lane] = h0;
    g_kh[kb + lane + 32] = h1;
    g_kl[kb + lane] = __float2bfloat16_rn(k0 - __bfloat162float(h0));
    g_kl[kb + lane + 32] = __float2bfloat16_rn(k1 - __bfloat162float(h1));
    size_t vb = (size_t)(b * HH + h) * DH * JJP;
    bf16 vh0 = __float2bfloat16_rn(v0);
    bf16 vh1 = __float2bfloat16_rn(v1);
    g_vth[vb + (size_t)lane * JJP + j] = vh0;
    g_vth[vb + (size_t)(lane + 32) * JJP + j] = vh1;
    g_vtl[vb + (size_t)lane * JJP + j] = __float2bfloat16_rn(v0 - __bfloat162float(vh0));
    g_vtl[vb + (size_t)(lane + 32) * JJP + j] = __float2bfloat16_rn(v1 - __bfloat162float(vh1));
}

__global__ void nullprep_kernel(const float* __restrict__ null_kv,
                                const float* __restrict__ ks) {
    int w = threadIdx.x >> 5;
    int lane = threadIdx.x & 31;
    int h = w / NNUL;
    int t = w % NNUL;
    const float* base = null_kv + (size_t)h * (2 * NNUL) * DH;
    float k0 = base[(2 * t) * DH + lane];
    float k1 = base[(2 * t) * DH + lane + 32];
    float v0 = base[(2 * t + 1) * DH + lane];
    float v1 = base[(2 * t + 1) * DH + lane + 32];
    float ss = k0 * k0 + k1 * k1;
#pragma unroll
    for (int off = 16; off; off >>= 1) ss += __shfl_xor_sync(0xffffffffu, ss, off);
    float inv = 1.0f / fmaxf(sqrtf(ss), 1e-12f);
    k0 = k0 * inv * ks[lane];
    k1 = k1 * inv * ks[lane + 32];
    bf16 kh0 = __float2bfloat16_rn(k0), kh1 = __float2bfloat16_rn(k1);
    bf16 kl0 = __float2bfloat16_rn(k0 - __bfloat162float(kh0));
    bf16 kl1 = __float2bfloat16_rn(k1 - __bfloat162float(kh1));
    bf16 vh0 = __float2bfloat16_rn(v0), vh1 = __float2bfloat16_rn(v1);
    bf16 vl0 = __float2bfloat16_rn(v0 - __bfloat162float(vh0));
    bf16 vl1 = __float2bfloat16_rn(v1 - __bfloat162float(vh1));
    for (int b = 0; b < BB; b++) {
        size_t kb = ((size_t)(b * HH + h) * JJP + t) * DH;
        g_kh[kb + lane] = kh0;
        g_kh[kb + lane + 32] = kh1;
        g_kl[kb + lane] = kl0;
        g_kl[kb + lane + 32] = kl1;
        size_t vb = (size_t)(b * HH + h) * DH * JJP;
        g_vth[vb + (size_t)lane * JJP + t] = vh0;
        g_vth[vb + (size_t)(lane + 32) * JJP + t] = vh1;
        g_vtl[vb + (size_t)lane * JJP + t] = vl0;
        g_vtl[vb + (size_t)(lane + 32) * JJP + t] = vl1;
    }
}

// ---------------- mma attention ----------------------------------------------
#define KSTR 72
#define QSTR 68
#define TILE_HB (64 * KSTR * 2)
#define ATTN_SMEM (4 * TILE_HB)

#define MMA_BF16(C, A, B0, B1)                                              \
    asm volatile(                                                           \
        "mma.sync.aligned.m16n8k16.row.col.f32.bf16.bf16.f32 "              \
        "{%0,%1,%2,%3}, {%4,%5,%6,%7}, {%8,%9}, {%0,%1,%2,%3};"             \
        : "+f"(C[0]), "+f"(C[1]), "+f"(C[2]), "+f"(C[3])                    \
        : "r"(A[0]), "r"(A[1]), "r"(A[2]), "r"(A[3]), "r"(B0), "r"(B1))

__device__ __forceinline__ uint32_t pack_bf2(float a, float b) {
    __nv_bfloat162 t;
    t.x = __float2bfloat16_rn(a);
    t.y = __float2bfloat16_rn(b);
    return *(uint32_t*)&t;
}

__global__ void __launch_bounds__(128)
attn_mma_kernel() {
    extern __shared__ char sm[];
    bf16* Kh = (bf16*)sm;
    bf16* Kl = (bf16*)(sm + TILE_HB);
    bf16* Vh = (bf16*)(sm + 2 * TILE_HB);
    bf16* Vl = (bf16*)(sm + 3 * TILE_HB);
    float* Qs = (float*)sm;

    int b = blockIdx.z, h = blockIdx.y;
    int qt = (gridDim.x - 1) - blockIdx.x;
    int tid = threadIdx.x;
    int w = tid >> 5;
    int lane = tid & 31;
    int fr = lane >> 2;
    int fc = lane & 3;

    size_t qbase = (size_t)((b * HH + h) * NN + qt * 64) * DH;
    const char* kh_b = (const char*)(g_kh + (size_t)(b * HH + h) * JJP * DH);
    const char* kl_b = (const char*)(g_kl + (size_t)(b * HH + h) * JJP * DH);
    const char* vth_b = (const char*)(g_vth + (size_t)(b * HH + h) * DH * JJP);
    const char* vtl_b = (const char*)(g_vtl + (size_t)(b * HH + h) * DH * JJP);

    for (int i = tid; i < 64 * 16; i += 128) {
        int r = i >> 4, c4 = (i & 15) * 4;
        *(float4*)&Qs[r * QSTR + c4] = *(const float4*)&g_q[qbase + (size_t)r * DH + c4];
    }
    __syncthreads();

    uint32_t qh[4][4], ql[4][4];
#pragma unroll
    for (int kc = 0; kc < 4; kc++) {
        int lr = w * 16 + fr;
        int c = kc * 16 + 2 * fc;
#pragma unroll
        for (int p = 0; p < 4; p++) {
            int rr = lr + (p & 1) * 8;
            int cc = c + (p >> 1) * 8;
            float x0 = Qs[rr * QSTR + cc], x1 = Qs[rr * QSTR + cc + 1];
            float h0 = __bfloat162float(__float2bfloat16_rn(x0));
            float h1 = __bfloat162float(__float2bfloat16_rn(x1));
            qh[kc][p] = pack_bf2(h0, h1);
            ql[kc][p] = pack_bf2(x0 - h0, x1 - h1);
        }
    }

    float O[8][4];
#pragma unroll
    for (int nb = 0; nb < 8; nb++)
#pragma unroll
        for (int r = 0; r < 4; r++) O[nb][r] = 0.f;

    float slope = exp2f(-0.5f * (float)(h + 1));
    int row0g = qt * 64 + w * 16 + fr;
    int row1g = row0g + 8;
    int my0 = row0g + NNUL, my1 = row1g + NNUL;
    float m0 = -1e30f, m1 = -1e30f, l0 = 0.f, l1 = 0.f;

    int nkeys = min(qt * 64 + 64 + NNUL, JJ);

    for (int j0 = 0; j0 < nkeys; j0 += 64) {
        __syncthreads();
        for (int i = tid; i < 64 * 8; i += 128) {
            int r = i >> 3, c = i & 7;
            uint32_t doff = r * 144 + c * 16;
            cp_async16(sm + 0 * TILE_HB + doff, kh_b + (size_t)(j0 + r) * 128 + c * 16);
            cp_async16(sm + 1 * TILE_HB + doff, kl_b + (size_t)(j0 + r) * 128 + c * 16);
            cp_async16(sm + 2 * TILE_HB + doff, vth_b + (size_t)r * (JJP * 2) + j0 * 2 + c * 16);
            cp_async16(sm + 3 * TILE_HB + doff, vtl_b + (size_t)r * (JJP * 2) + j0 * 2 + c * 16);
        }
        cp_commit();
        cp_wait0();
        __syncthreads();

        float S[8][4];
#pragma unroll
        for (int nb = 0; nb < 8; nb++)
#pragma unroll
            for (int r = 0; r < 4; r++) S[nb][r] = 0.f;

#pragma unroll
        for (int kc = 0; kc < 4; kc++) {
#pragma unroll
            for (int nb = 0; nb < 8; nb++) {
                int krow = nb * 8 + fr;
                int kcol = kc * 16 + 2 * fc;
                uint32_t b0h = *(uint32_t*)&Kh[krow * KSTR + kcol];
                uint32_t b1h = *(uint32_t*)&Kh[krow * KSTR + kcol + 8];
                uint32_t b0l = *(uint32_t*)&Kl[krow * KSTR + kcol];
                uint32_t b1l = *(uint32_t*)&Kl[krow * KSTR + kcol + 8];
                MMA_BF16(S[nb], qh[kc], b0h, b1h);
                MMA_BF16(S[nb], qh[kc], b0l, b1l);
                MMA_BF16(S[nb], ql[kc], b0h, b1h);
            }
        }

        float mt0 = -1e30f, mt1 = -1e30f;
#pragma unroll
        for (int nb = 0; nb < 8; nb++) {
#pragma unroll
            for (int e = 0; e < 2; e++) {
                int col = j0 + nb * 8 + 2 * fc + e;
                float s0 = S[nb][e] * SCALE + slope * (float)(col - my0);
                if (col > my0) s0 = -1e30f;
                S[nb][e] = s0;
                mt0 = fmaxf(mt0, s0);
                float s1 = S[nb][2 + e] * SCALE + slope * (float)(col - my1);
                if (col > my1) s1 = -1e30f;
                S[nb][2 + e] = s1;
                mt1 = fmaxf(mt1, s1);
            }
        }
#pragma unroll
        for (int off = 1; off <= 2; off <<= 1) {
            mt0 = fmaxf(mt0, __shfl_xor_sync(0xffffffffu, mt0, off));
            mt1 = fmaxf(mt1, __shfl_xor_sync(0xffffffffu, mt1, off));
        }
        float mn0 = fmaxf(m0, mt0), mn1 = fmaxf(m1, mt1);
        float c0 = __expf(m0 - mn0), c1 = __expf(m1 - mn1);
        m0 = mn0; m1 = mn1;

        float ps0 = 0.f, ps1 = 0.f;
#pragma unroll
        for (int nb = 0; nb < 8; nb++) {
#pragma unroll
            for (int e = 0; e < 2; e++) {
                float p0 = __expf(S[nb][e] - m0);
                float p1 = __expf(S[nb][2 + e] - m1);
                S[nb][e] = p0; S[nb][2 + e] = p1;
                ps0 += p0; ps1 += p1;
            }
        }
        l0 = l0 * c0 + ps0;
        l1 = l1 * c1 + ps1;
#pragma unroll
        for (int nb = 0; nb < 8; nb++) {
            O[nb][0] *= c0; O[nb][1] *= c0;
            O[nb][2] *= c1; O[nb][3] *= c1;
        }

        uint32_t ph[4][4], pl[4][4];
#pragma unroll
        for (int kc = 0; kc < 4; kc++) {
#pragma unroll
            for (int p = 0; p < 4; p++) {
                float x0 = S[2 * kc + (p >> 1)][(p & 1) * 2 + 0];
                float x1 = S[2 * kc + (p >> 1)][(p & 1) * 2 + 1];
                float h0 = __bfloat162float(__float2bfloat16_rn(x0));
                float h1 = __bfloat162float(__float2bfloat16_rn(x1));
                ph[kc][p] = pack_bf2(h0, h1);
                pl[kc][p] = pack_bf2(x0 - h0, x1 - h1);
            }
        }

#pragma unroll
        for (int kc = 0; kc < 4; kc++) {
#pragma unroll
            for (int nb = 0; nb < 8; nb++) {
                int drow = nb * 8 + fr;
                int kcol = kc * 16 + 2 * fc;
                uint32_t b0h = *(uint32_t*)&Vh[drow * KSTR + kcol];
                uint32_t b1h = *(uint32_t*)&Vh[drow * KSTR + kcol + 8];
                uint32_t b0l = *(uint32_t*)&Vl[drow * KSTR + kcol];
                uint32_t b1l = *(uint32_t*)&Vl[drow * KSTR + kcol + 8];
                MMA_BF16(O[nb], ph[kc], b0h, b1h);
                MMA_BF16(O[nb], ph[kc], b0l, b1l);
                MMA_BF16(O[nb], pl[kc], b0h, b1h);
            }
        }
    }

#pragma unroll
    for (int off = 1; off <= 2; off <<= 1) {
        l0 += __shfl_xor_sync(0xffffffffu, l0, off);
        l1 += __shfl_xor_sync(0xffffffffu, l1, off);
    }
    float i0 = 1.0f / l0, i1 = 1.0f / l1;
#pragma unroll
    for (int nb = 0; nb < 8; nb++) {
        int col = h * DH + nb * 8 + 2 * fc;
        *(float2*)&g_ao[(size_t)(b * NN + row0g) * DIM + col] =
            make_float2(tf32f(O[nb][0] * i0), tf32f(O[nb][1] * i0));
        *(float2*)&g_ao[(size_t)(b * NN + row1g) * DIM + col] =
            make_float2(tf32f(O[nb][2] * i1), tf32f(O[nb][3] * i1));
    }
}

// ---------------- launch -----------------------------------------------------
extern "C" void kernel_launch(void* const* d_in, const int* in_sizes, int n_in,
                              void* d_out, int out_size) {
    const float* x = (const float*)d_in[0];
    const float* norm_g = (const float*)d_in[1];
    const float* norm_b = (const float*)d_in[2];
    const float* Wq = (const float*)d_in[3];
    const float* Wkv = (const float*)d_in[4];
    const float* q_scale = (const float*)d_in[5];
    const float* k_scale = (const float*)d_in[6];
    const float* null_kv = (const float*)d_in[7];
    const float* Wout = (const float*)d_in[8];
    float* out = (float*)d_out;

    float *p_wqt, *p_wkvt, *p_wot;
    cudaGetSymbolAddress((void**)&p_wqt, g_wqt);
    cudaGetSymbolAddress((void**)&p_wkvt, g_wkvt);
    cudaGetSymbolAddress((void**)&p_wot, g_wot);

    static int smem_set = 0;
    if (!smem_set) {
        cudaFuncSetAttribute(tf32gemm_qkv, cudaFuncAttributeMaxDynamicSharedMemorySize,
                             GEMM_SMEM_BYTES);
        cudaFuncSetAttribute(tf32gemm_o, cudaFuncAttributeMaxDynamicSharedMemorySize,
                             GEMM_SMEM_BYTES);
        cudaFuncSetAttribute(attn_mma_kernel, cudaFuncAttributeMaxDynamicSharedMemorySize,
                             ATTN_SMEM);
        smem_set = 1;
    }

    // 1-3: weight transpose-converts + LN (launch 4 = fused QKV gemm for ncu)
    wtconv_kernel<<<dim3(DIM / 32, DIM / 32), dim3(32, 8)>>>(Wq, p_wqt, DIM, DIM);
    wtconv_kernel<<<dim3(2 * DIM / 32, DIM / 32), dim3(32, 8)>>>(Wkv, p_wkvt, DIM, 2 * DIM);
    ln_kernel<<<MM, 256>>>(x, norm_g, norm_b);

    // 4: fused Q + KV projections
    tf32gemm_qkv<<<dim3(24, MM / TBM), 256, GEMM_SMEM_BYTES>>>();

    // 5: Wout transpose-convert (independent)
    wtconv_kernel<<<dim3(DIM / 32, DIM / 32), dim3(32, 8)>>>(Wout, p_wot, DIM, DIM);

    // 6-8: preps
    qprep_kernel<<<(BB * NN * HH) / 4, 128>>>(q_scale);
    kvprep_kernel<<<(BB * NN * HH) / 4, 128>>>(k_scale);
    nullprep_kernel<<<1, HH * NNUL * 32>>>(null_kv, k_scale);

    // 9: attention
    attn_mma_kernel<<<dim3(NN / 64, HH, BB), 128, ATTN_SMEM>>>();

    // 10: output projection
    tf32gemm_o<<<dim3(DIM / TBN, MM / TBM), 256, GEMM_SMEM_BYTES>>>(out);
}